// round 5
// baseline (speedup 1.0000x reference)
#include <cuda_runtime.h>
#include <cuda_bf16.h>
#include <cstdint>
#include <cstddef>

// ---------------------------------------------------------------------------
// GraphSAGE on sm_100 (base target):
//   CSR build: init -> count -> single-pass scan (decoupled aggregates) -> fill
//   3x fused [ gather+mean -> dual GEMM (mma.sync bf16 3-term) -> bias+relu ]
//   final 128->64 linear (same GEMM core, no gather)
//
// Fusion: each CTA owns 128 dst nodes; it gathers neighbor means from X
// (L2-resident) straight into smem split-bf16 tiles, then runs the dual GEMM
// [X|agg] @ [Ws;Wn] (K=256) with A-chunk double buffering and cp.async
// double-buffered weights.  No g_agg round trip.
// Precision: x = hi + lo (bf16); x*w ~ hi*whi + lo*whi + hi*wlo (3 terms).
// ---------------------------------------------------------------------------

#define N_NODES 100000
#define N_EDGES 600000
#define F 128

// ---- scratch ---------------------------------------------------------------
__device__ float g_hbuf0[(size_t)N_NODES * F];
__device__ float g_hbuf1[(size_t)N_NODES * F];
__device__ float g_invdeg[N_NODES];
__device__ int   g_deg[N_NODES];
__device__ int   g_cursor[N_NODES];
__device__ int   g_csr_off[N_NODES + 1];
__device__ int   g_csr_src[N_EDGES];
__device__ int   g_blockagg[128];
// bf16 hi/lo weights, [n][k]: layers 0..2: n 0..127, k 0..255 (k<128 self,
// else neigh); final: n 0..63, k 0..127.
#define W_TOTAL (3 * 128 * 256 + 64 * 128)
__device__ __nv_bfloat16 g_whi[W_TOTAL];
__device__ __nv_bfloat16 g_wlo[W_TOTAL];

// ---- helpers ---------------------------------------------------------------
__device__ __forceinline__ uint32_t smem_u32(const void* p) {
    uint32_t a;
    asm("{ .reg .u64 t; cvta.to.shared.u64 t, %1; cvt.u32.u64 %0, t; }"
        : "=r"(a) : "l"(p));
    return a;
}
__device__ __forceinline__ void mma16816(float* c, const uint32_t* a,
                                         const uint32_t* b) {
    asm volatile(
        "mma.sync.aligned.m16n8k16.row.col.f32.bf16.bf16.f32 "
        "{%0,%1,%2,%3}, {%4,%5,%6,%7}, {%8,%9}, {%0,%1,%2,%3};"
        : "+f"(c[0]), "+f"(c[1]), "+f"(c[2]), "+f"(c[3])
        : "r"(a[0]), "r"(a[1]), "r"(a[2]), "r"(a[3]), "r"(b[0]), "r"(b[1]));
}
__device__ __forceinline__ void ldsm4(uint32_t* r, uint32_t addr) {
    asm volatile(
        "ldmatrix.sync.aligned.m8n8.x4.shared.b16 {%0,%1,%2,%3}, [%4];"
        : "=r"(r[0]), "=r"(r[1]), "=r"(r[2]), "=r"(r[3]) : "r"(addr));
}
#define SWZ(o) ((o) ^ (((o) >> 3) & 0x70))
// pack two floats as bf16x2 (low = a, high = b)
__device__ __forceinline__ uint32_t pk_bf16(float a, float b) {
    uint32_t r;
    asm("cvt.rn.bf16x2.f32 %0, %1, %2;" : "=r"(r) : "f"(b), "f"(a));
    return r;
}
__device__ __forceinline__ float lo_f(uint32_t p) {
    return __uint_as_float(p << 16);
}
__device__ __forceinline__ float hi_f(uint32_t p) {
    return __uint_as_float(p & 0xFFFF0000u);
}
__device__ __forceinline__ void cp16(uint32_t d, const void* s) {
    asm volatile("cp.async.cg.shared.global [%0], [%1], 16;" ::"r"(d), "l"(s)
                 : "memory");
}
#define CP_COMMIT asm volatile("cp.async.commit_group;" ::: "memory")
#define CP_WAIT0 asm volatile("cp.async.wait_group 0;" ::: "memory")

// ---- CSR build -------------------------------------------------------------
__global__ void init_kernel() {
    int i = blockIdx.x * blockDim.x + threadIdx.x;
    if (i < N_NODES) { g_deg[i] = 0; g_cursor[i] = 0; }
    if (i < 128) g_blockagg[i] = 0;
}
__global__ void count_kernel(const int* __restrict__ dst) {
    int e = blockIdx.x * blockDim.x + threadIdx.x;
    if (e < N_EDGES) atomicAdd(&g_deg[dst[e]], 1);
}
// single-pass scan: all blocks resident; publish block aggregate via atomic,
// warp-parallel lookback over predecessors, then write csr_off + invdeg.
__global__ void scanall_kernel() {
    __shared__ int ws[32];
    __shared__ int s_base;
    const int tid = threadIdx.x, lane = tid & 31, w = tid >> 5;
    const int bid = blockIdx.x;
    const int i = bid * 1024 + tid;
    const int x = (i < N_NODES) ? g_deg[i] : 0;
    int inc = x;
    #pragma unroll
    for (int o = 1; o < 32; o <<= 1) {
        int v = __shfl_up_sync(0xFFFFFFFF, inc, o);
        if (lane >= o) inc += v;
    }
    if (lane == 31) ws[w] = inc;
    __syncthreads();
    if (w == 0) {
        int s = ws[lane];
        #pragma unroll
        for (int o = 1; o < 32; o <<= 1) {
            int v = __shfl_up_sync(0xFFFFFFFF, s, o);
            if (lane >= o) s += v;
        }
        ws[lane] = s;
    }
    __syncthreads();
    const int local_excl = ((w == 0) ? 0 : ws[w - 1]) + inc - x;
    const int T = ws[31];
    if (tid == 0) atomicExch(&g_blockagg[bid], T | (1 << 30));
    if (w == 0) {
        int sum = 0;
        for (int j = lane; j < bid; j += 32) {
            int v;
            do { v = atomicAdd(&g_blockagg[j], 0); } while (v == 0);
            sum += v & 0x3FFFFFFF;
        }
        #pragma unroll
        for (int o = 16; o > 0; o >>= 1)
            sum += __shfl_down_sync(0xFFFFFFFF, sum, o);
        if (lane == 0) s_base = sum;
    }
    __syncthreads();
    if (i < N_NODES) {
        g_csr_off[i] = s_base + local_excl;
        g_invdeg[i] = 1.0f / fmaxf((float)x, 1.0f);
    }
    if (i == 0) g_csr_off[N_NODES] = N_EDGES;
}
__global__ void fill_kernel(const int* __restrict__ src,
                            const int* __restrict__ dst) {
    int e = blockIdx.x * blockDim.x + threadIdx.x;
    if (e < N_EDGES) {
        int d = dst[e];
        int pos = g_csr_off[d] + atomicAdd(&g_cursor[d], 1);
        g_csr_src[pos] = src[e];
    }
}

// ---- weight pre-split: fp32 -> bf16 hi/lo, [n][k] concat layout ------------
__global__ void wconv_kernel(const float* w0s, const float* w0n,
                             const float* w1s, const float* w1n,
                             const float* w2s, const float* w2n,
                             const float* wo) {
    int idx = blockIdx.x * blockDim.x + threadIdx.x;
    if (idx >= W_TOTAL) return;
    float w;
    if (idx < 3 * 32768) {
        int l = idx >> 15, local = idx & 32767;
        int n = local >> 8, k = local & 255;
        const float* ws = (l == 0) ? w0s : (l == 1) ? w1s : w2s;
        const float* wn = (l == 0) ? w0n : (l == 1) ? w1n : w2n;
        w = (k < 128) ? ws[k * 128 + n] : wn[(k - 128) * 128 + n];
    } else {
        int local = idx - 3 * 32768;
        int n = local >> 7, k = local & 127;
        w = wo[k * 64 + n];
    }
    __nv_bfloat16 hi = __float2bfloat16(w);
    g_whi[idx] = hi;
    g_wlo[idx] = __float2bfloat16(w - __bfloat162float(hi));
}

// ---- fused gather + mma.sync bf16 3-term GEMM ------------------------------
// AGG: dual layer, K=256 = [self(128) | gathered-mean(128)]; else K=128 self.
template <int N_OUT, bool AGG, bool RELU>
__global__ void __launch_bounds__(256) sage_fused(
    const float* __restrict__ X,
    const __nv_bfloat16* __restrict__ Whi,
    const __nv_bfloat16* __restrict__ Wlo,
    const float* __restrict__ bsv, const float* __restrict__ bnv,
    float* __restrict__ Y) {
    constexpr int KTOT = AGG ? 256 : 128;
    constexpr int NCH = KTOT / 64;
    constexpr int NWN = N_OUT / 32;
    constexpr int MI = 128 / (8 / NWN) / 16;
    constexpr int BT = N_OUT * 128;                 // bytes per B plane tile
    constexpr int OFF_AGG = 65536;                  // 4x16KB agg tiles
    constexpr int OFF_B = AGG ? 131072 : 65536;     // 2 bufs x {hi,lo}
    constexpr int OFF_BIAS = OFF_B + 4 * BT;

    extern __shared__ char smc[];
    const uint32_t sb = smem_u32(smc);
    const int tid = threadIdx.x, wid = tid >> 5, lane = tid & 31;
    const int node0 = blockIdx.x * 128;
    float* sB = (float*)(smc + OFF_BIAS);
    if (tid < N_OUT) sB[tid] = bsv[tid] + (AGG ? bnv[tid] : 0.0f);

    // ---- producers --------------------------------------------------------
    auto cpasyncB = [&](int c) {
        const uint32_t dbase = sb + OFF_B + (c & 1) * (2 * BT);
        #pragma unroll
        for (int g = tid; g < N_OUT * 8; g += 256) {
            int n = g >> 3, kk = (g & 7) * 8;
            uint32_t doff = SWZ((uint32_t)(n * 128 + kk * 2));
            const int so = n * KTOT + c * 64 + kk;
            cp16(dbase + doff, Whi + so);
            cp16(dbase + BT + doff, Wlo + so);
        }
        CP_COMMIT;
    };
    float4 st[8];
    const int arow = tid >> 1;
    const int acolb = (tid & 1) * 32;
    const int pnode = node0 + arow;
    auto do_ldgA = [&](int c) {
        if (pnode < N_NODES) {
            const float4* p =
                (const float4*)(X + (size_t)pnode * F + c * 64 + acolb);
            #pragma unroll
            for (int j = 0; j < 8; j++) st[j] = p[j];
        } else {
            #pragma unroll
            for (int j = 0; j < 8; j++) st[j] = make_float4(0.f, 0.f, 0.f, 0.f);
        }
    };
    auto do_stsA = [&](int b) {
        char* dhi = smc + b * 32768;
        char* dlo = dhi + 16384;
        #pragma unroll
        for (int j = 0; j < 4; j++) {
            float4 v0 = st[2 * j], v1 = st[2 * j + 1];
            uint4 H, L;
            H.x = pk_bf16(v0.x, v0.y); H.y = pk_bf16(v0.z, v0.w);
            H.z = pk_bf16(v1.x, v1.y); H.w = pk_bf16(v1.z, v1.w);
            L.x = pk_bf16(v0.x - lo_f(H.x), v0.y - hi_f(H.x));
            L.y = pk_bf16(v0.z - lo_f(H.y), v0.w - hi_f(H.y));
            L.z = pk_bf16(v1.x - lo_f(H.z), v1.y - hi_f(H.z));
            L.w = pk_bf16(v1.z - lo_f(H.w), v1.w - hi_f(H.w));
            uint32_t off = SWZ((uint32_t)(arow * 128 + (acolb + 8 * j) * 2));
            *(uint4*)(dhi + off) = H;
            *(uint4*)(dlo + off) = L;
        }
    };

    // ---- prologue: B0 + A0 in flight, gather overlaps ---------------------
    cpasyncB(0);
    do_ldgA(0);
    if (AGG) {
        // warp-per-16-nodes gather + mean -> split bf16 agg tiles
        const int gtile = lane >> 4;               // cols<64 -> chunk2 tile
        const int gcol = (lane * 4) & 63;
        char* hbase = smc + OFF_AGG + gtile * 32768;
        #pragma unroll 1
        for (int j = 0; j < 16; j++) {
            const int node = node0 + wid * 16 + j;
            float4 acc = make_float4(0.f, 0.f, 0.f, 0.f);
            float inv = 0.f;
            if (node < N_NODES) {
                const int beg = g_csr_off[node], end = g_csr_off[node + 1];
                inv = g_invdeg[node];
                for (int e = beg; e < end; e++) {
                    const int s = g_csr_src[e];
                    float4 v = *(const float4*)&X[(size_t)s * F + lane * 4];
                    acc.x += v.x; acc.y += v.y; acc.z += v.z; acc.w += v.w;
                }
            }
            const float ax = acc.x * inv, ay = acc.y * inv;
            const float az = acc.z * inv, aw = acc.w * inv;
            uint32_t H0 = pk_bf16(ax, ay), H1 = pk_bf16(az, aw);
            uint32_t L0 = pk_bf16(ax - lo_f(H0), ay - hi_f(H0));
            uint32_t L1 = pk_bf16(az - lo_f(H1), aw - hi_f(H1));
            uint32_t o = SWZ((uint32_t)((wid * 16 + j) * 128 + gcol * 2));
            *(uint2*)(hbase + o) = make_uint2(H0, H1);
            *(uint2*)(hbase + 16384 + o) = make_uint2(L0, L1);
        }
    }
    do_stsA(0);
    CP_WAIT0;
    __syncthreads();

    // ---- lane-invariant ldmatrix bases ------------------------------------
    const int wn = (wid % NWN) * 32;
    const int wm = (wid / NWN) * (MI * 16);
    const int ar = wm + (lane & 15);
    const uint32_t a_base = (uint32_t)(ar * 128 + (lane >> 4) * 16);
    const uint32_t a_mask = (uint32_t)((ar & 7) << 4);
    const int br = wn + (lane & 7) + ((lane >> 4) << 3);
    const uint32_t b_base = (uint32_t)(br * 128 + ((lane >> 3) & 1) * 16);
    const uint32_t b_mask = (uint32_t)((br & 7) << 4);

    float acc[MI][4][4];
    #pragma unroll
    for (int mi = 0; mi < MI; mi++)
        #pragma unroll
        for (int ni = 0; ni < 4; ni++)
            #pragma unroll
            for (int q = 0; q < 4; q++) acc[mi][ni][q] = 0.f;

    // ---- chunk loop --------------------------------------------------------
    #pragma unroll 1
    for (int c = 0; c < NCH; c++) {
        if (c + 1 < 2) do_ldgA(c + 1);
        if (c + 1 < NCH) cpasyncB(c + 1);
        const uint32_t ahi = (AGG && c >= 2)
                                 ? sb + OFF_AGG + (c - 2) * 32768
                                 : sb + (c & 1) * 32768;
        const uint32_t alo = ahi + 16384;
        const uint32_t bhib = sb + OFF_B + (c & 1) * (2 * BT);
        const uint32_t blob = bhib + BT;
        #pragma unroll
        for (int ks = 0; ks < 4; ks++) {
            uint32_t ah[MI][4], al[MI][4], bh[4][2], bl[4][2];
            const uint32_t ka = (a_base + ks * 32) ^ a_mask;
            #pragma unroll
            for (int mi = 0; mi < MI; mi++) {
                ldsm4(ah[mi], ahi + ka + mi * 2048);
                ldsm4(al[mi], alo + ka + mi * 2048);
            }
            const uint32_t kb = (b_base + ks * 32) ^ b_mask;
            ldsm4(&bh[0][0], bhib + kb);
            ldsm4(&bh[2][0], bhib + kb + 2048);
            ldsm4(&bl[0][0], blob + kb);
            ldsm4(&bl[2][0], blob + kb + 2048);
            #pragma unroll
            for (int mi = 0; mi < MI; mi++)
                #pragma unroll
                for (int ni = 0; ni < 4; ni++)
                    mma16816(acc[mi][ni], ah[mi], bh[ni]);
            #pragma unroll
            for (int mi = 0; mi < MI; mi++)
                #pragma unroll
                for (int ni = 0; ni < 4; ni++)
                    mma16816(acc[mi][ni], al[mi], bh[ni]);
            #pragma unroll
            for (int mi = 0; mi < MI; mi++)
                #pragma unroll
                for (int ni = 0; ni < 4; ni++)
                    mma16816(acc[mi][ni], ah[mi], bl[ni]);
        }
        if (c + 1 < NCH) {
            if (c + 1 < 2) do_stsA((c + 1) & 1);
            CP_WAIT0;
            __syncthreads();
        }
    }

    // ---- epilogue ----------------------------------------------------------
    const int erow = wm + (lane >> 2);
    const int ecol = wn + (lane & 3) * 2;
    #pragma unroll
    for (int mi = 0; mi < MI; mi++) {
        #pragma unroll
        for (int h = 0; h < 2; h++) {
            const int gr = node0 + erow + mi * 16 + h * 8;
            if (gr >= N_NODES) continue;
            float* yp = Y + (size_t)gr * N_OUT;
            #pragma unroll
            for (int ni = 0; ni < 4; ni++) {
                float2 o;
                o.x = acc[mi][ni][2 * h] + sB[ecol + ni * 8];
                o.y = acc[mi][ni][2 * h + 1] + sB[ecol + ni * 8 + 1];
                if (RELU) { o.x = fmaxf(o.x, 0.f); o.y = fmaxf(o.y, 0.f); }
                *(float2*)(yp + ecol + ni * 8) = o;
            }
        }
    }
}

// ---------------------------------------------------------------------------
extern "C" void kernel_launch(void* const* d_in, const int* in_sizes, int n_in,
                              void* d_out, int out_size) {
    const float* feats = (const float*)d_in[0];
    const int* src = (const int*)d_in[1];
    const int* dst = (const int*)d_in[2];
    const float* Ws[3] = {(const float*)d_in[3], (const float*)d_in[7],
                          (const float*)d_in[11]};
    const float* bs[3] = {(const float*)d_in[4], (const float*)d_in[8],
                          (const float*)d_in[12]};
    const float* Wn[3] = {(const float*)d_in[5], (const float*)d_in[9],
                          (const float*)d_in[13]};
    const float* bn[3] = {(const float*)d_in[6], (const float*)d_in[10],
                          (const float*)d_in[14]};
    const float* Wout = (const float*)d_in[15];
    const float* bout = (const float*)d_in[16];

    float *h0, *h1;
    __nv_bfloat16 *whi, *wlo;
    cudaGetSymbolAddress((void**)&h0, g_hbuf0);
    cudaGetSymbolAddress((void**)&h1, g_hbuf1);
    cudaGetSymbolAddress((void**)&whi, g_whi);
    cudaGetSymbolAddress((void**)&wlo, g_wlo);

    // smem: selfA 64KB [+ agg 64KB] + B 4 plane-bufs + bias
    const int SMEM_DUAL = 131072 + 4 * 128 * 128 + 512;  // 197,120
    const int SMEM_FIN = 65536 + 4 * 64 * 128 + 256;     //  98,560

    auto kRelu = sage_fused<128, true, true>;
    auto kNoRelu = sage_fused<128, true, false>;
    auto kFinal = sage_fused<64, false, false>;
    cudaFuncSetAttribute((const void*)kRelu,
                         cudaFuncAttributeMaxDynamicSharedMemorySize, SMEM_DUAL);
    cudaFuncSetAttribute((const void*)kNoRelu,
                         cudaFuncAttributeMaxDynamicSharedMemorySize, SMEM_DUAL);
    cudaFuncSetAttribute((const void*)kFinal,
                         cudaFuncAttributeMaxDynamicSharedMemorySize, SMEM_FIN);

    const int NPART = (N_NODES + 1023) / 1024;  // 98
    init_kernel<<<(N_NODES + 255) / 256, 256>>>();
    count_kernel<<<(N_EDGES + 255) / 256, 256>>>(dst);
    scanall_kernel<<<NPART, 1024>>>();
    fill_kernel<<<(N_EDGES + 255) / 256, 256>>>(src, dst);
    wconv_kernel<<<(W_TOTAL + 255) / 256, 256>>>(Ws[0], Wn[0], Ws[1], Wn[1],
                                                 Ws[2], Wn[2], Wout);

    const int GB = (N_NODES + 127) / 128;  // 782
    kRelu<<<GB, 256, SMEM_DUAL>>>(feats, whi, wlo, bs[0], bn[0], h0);
    kRelu<<<GB, 256, SMEM_DUAL>>>(h0, whi + 32768, wlo + 32768, bs[1], bn[1],
                                  h1);
    kNoRelu<<<GB, 256, SMEM_DUAL>>>(h1, whi + 65536, wlo + 65536, bs[2], bn[2],
                                    h0);
    kFinal<<<GB, 256, SMEM_FIN>>>(h0, whi + 98304, wlo + 98304, bout, nullptr,
                                  (float*)d_out);
}

// round 6
// speedup vs baseline: 1.5898x; 1.5898x over previous
#include <cuda_runtime.h>
#include <cuda_bf16.h>
#include <cstdint>
#include <cstddef>

// ---------------------------------------------------------------------------
// GraphSAGE on sm_100 (base target):
//   CSR: init -> count -> single-pass scan (decoupled lookback) -> fill
//   3x [ agg (warp/node segment-mean) ; dual GEMM mma.sync bf16 3-term ]
//   final 128->64 linear
//
// Dual GEMM: X*Ws + XN*Wn == [X|XN] @ [Ws;Wn] -> one GEMM, K=256.
// Precision: x = hi + lo (bf16); x*w ~ hi*whi + lo*whi + hi*wlo (3 terms).
// GEMM CTA: 512 threads (16 warps = 4/SMSP for latency hiding), tile
// 128(M) x N_OUT; A chunks double-buffered via register-staged LDG; B chunks
// (32KB) double-buffered via cp.async.  smem ~131.6KB.
// ---------------------------------------------------------------------------

#define N_NODES 100000
#define N_EDGES 600000
#define F 128

// ---- scratch ---------------------------------------------------------------
__device__ float g_hbuf0[(size_t)N_NODES * F];
__device__ float g_hbuf1[(size_t)N_NODES * F];
__device__ float g_agg[(size_t)N_NODES * F];
__device__ float g_invdeg[N_NODES];
__device__ int   g_deg[N_NODES];
__device__ int   g_cursor[N_NODES];
__device__ int   g_csr_off[N_NODES + 1];
__device__ int   g_csr_src[N_EDGES];
__device__ int   g_blockagg[128];
// bf16 hi/lo weights, [n][k]: layers 0..2: n 0..127, k 0..255 (k<128 self,
// else neigh); final: n 0..63, k 0..127.
#define W_TOTAL (3 * 128 * 256 + 64 * 128)
__device__ __nv_bfloat16 g_whi[W_TOTAL];
__device__ __nv_bfloat16 g_wlo[W_TOTAL];

// ---- helpers ---------------------------------------------------------------
__device__ __forceinline__ uint32_t smem_u32(const void* p) {
    uint32_t a;
    asm("{ .reg .u64 t; cvta.to.shared.u64 t, %1; cvt.u32.u64 %0, t; }"
        : "=r"(a) : "l"(p));
    return a;
}
__device__ __forceinline__ void mma16816(float* c, const uint32_t* a,
                                         const uint32_t* b) {
    asm volatile(
        "mma.sync.aligned.m16n8k16.row.col.f32.bf16.bf16.f32 "
        "{%0,%1,%2,%3}, {%4,%5,%6,%7}, {%8,%9}, {%0,%1,%2,%3};"
        : "+f"(c[0]), "+f"(c[1]), "+f"(c[2]), "+f"(c[3])
        : "r"(a[0]), "r"(a[1]), "r"(a[2]), "r"(a[3]), "r"(b[0]), "r"(b[1]));
}
__device__ __forceinline__ void ldsm4(uint32_t* r, uint32_t addr) {
    asm volatile(
        "ldmatrix.sync.aligned.m8n8.x4.shared.b16 {%0,%1,%2,%3}, [%4];"
        : "=r"(r[0]), "=r"(r[1]), "=r"(r[2]), "=r"(r[3]) : "r"(addr));
}
#define SWZ(o) ((o) ^ (((o) >> 3) & 0x70))
// pack two floats as bf16x2 (low = a, high = b)
__device__ __forceinline__ uint32_t pk_bf16(float a, float b) {
    uint32_t r;
    asm("cvt.rn.bf16x2.f32 %0, %1, %2;" : "=r"(r) : "f"(b), "f"(a));
    return r;
}
__device__ __forceinline__ float lo_f(uint32_t p) {
    return __uint_as_float(p << 16);
}
__device__ __forceinline__ float hi_f(uint32_t p) {
    return __uint_as_float(p & 0xFFFF0000u);
}
__device__ __forceinline__ void cp16(uint32_t d, const void* s) {
    asm volatile("cp.async.cg.shared.global [%0], [%1], 16;" ::"r"(d), "l"(s)
                 : "memory");
}
#define CP_COMMIT asm volatile("cp.async.commit_group;" ::: "memory")
#define CP_WAIT0 asm volatile("cp.async.wait_group 0;" ::: "memory")

// ---- CSR build -------------------------------------------------------------
__global__ void init_kernel() {
    int i = blockIdx.x * blockDim.x + threadIdx.x;
    if (i < N_NODES) { g_deg[i] = 0; g_cursor[i] = 0; }
    if (i < 128) g_blockagg[i] = 0;
}
__global__ void count_kernel(const int* __restrict__ dst) {
    int e = blockIdx.x * blockDim.x + threadIdx.x;
    if (e < N_EDGES) atomicAdd(&g_deg[dst[e]], 1);
}
// single-pass scan: publish block aggregate, warp-parallel lookback.
__global__ void scanall_kernel() {
    __shared__ int ws[32];
    __shared__ int s_base;
    const int tid = threadIdx.x, lane = tid & 31, w = tid >> 5;
    const int bid = blockIdx.x;
    const int i = bid * 1024 + tid;
    const int x = (i < N_NODES) ? g_deg[i] : 0;
    int inc = x;
    #pragma unroll
    for (int o = 1; o < 32; o <<= 1) {
        int v = __shfl_up_sync(0xFFFFFFFF, inc, o);
        if (lane >= o) inc += v;
    }
    if (lane == 31) ws[w] = inc;
    __syncthreads();
    if (w == 0) {
        int s = ws[lane];
        #pragma unroll
        for (int o = 1; o < 32; o <<= 1) {
            int v = __shfl_up_sync(0xFFFFFFFF, s, o);
            if (lane >= o) s += v;
        }
        ws[lane] = s;
    }
    __syncthreads();
    const int local_excl = ((w == 0) ? 0 : ws[w - 1]) + inc - x;
    const int T = ws[31];
    if (tid == 0) atomicExch(&g_blockagg[bid], T | (1 << 30));
    if (w == 0) {
        int sum = 0;
        for (int j = lane; j < bid; j += 32) {
            int v;
            do { v = atomicAdd(&g_blockagg[j], 0); } while (v == 0);
            sum += v & 0x3FFFFFFF;
        }
        #pragma unroll
        for (int o = 16; o > 0; o >>= 1)
            sum += __shfl_down_sync(0xFFFFFFFF, sum, o);
        if (lane == 0) s_base = sum;
    }
    __syncthreads();
    if (i < N_NODES) {
        g_csr_off[i] = s_base + local_excl;
        g_invdeg[i] = 1.0f / fmaxf((float)x, 1.0f);
    }
    if (i == 0) g_csr_off[N_NODES] = N_EDGES;
}
__global__ void fill_kernel(const int* __restrict__ src,
                            const int* __restrict__ dst) {
    int e = blockIdx.x * blockDim.x + threadIdx.x;
    if (e < N_EDGES) {
        int d = dst[e];
        int pos = g_csr_off[d] + atomicAdd(&g_cursor[d], 1);
        g_csr_src[pos] = src[e];
    }
}

// ---- weight pre-split: fp32 -> bf16 hi/lo, [n][k] concat layout ------------
__global__ void wconv_kernel(const float* w0s, const float* w0n,
                             const float* w1s, const float* w1n,
                             const float* w2s, const float* w2n,
                             const float* wo) {
    int idx = blockIdx.x * blockDim.x + threadIdx.x;
    if (idx >= W_TOTAL) return;
    float w;
    if (idx < 3 * 32768) {
        int l = idx >> 15, local = idx & 32767;
        int n = local >> 8, k = local & 255;
        const float* ws = (l == 0) ? w0s : (l == 1) ? w1s : w2s;
        const float* wn = (l == 0) ? w0n : (l == 1) ? w1n : w2n;
        w = (k < 128) ? ws[k * 128 + n] : wn[(k - 128) * 128 + n];
    } else {
        int local = idx - 3 * 32768;
        int n = local >> 7, k = local & 127;
        w = wo[k * 64 + n];
    }
    __nv_bfloat16 hi = __float2bfloat16(w);
    g_whi[idx] = hi;
    g_wlo[idx] = __float2bfloat16(w - __bfloat162float(hi));
}

// ---- aggregation: warp per node, segment mean ------------------------------
__global__ void agg_kernel(const float* __restrict__ X) {
    int w = (blockIdx.x * blockDim.x + threadIdx.x) >> 5;
    int lane = threadIdx.x & 31;
    if (w >= N_NODES) return;
    int beg = g_csr_off[w], end = g_csr_off[w + 1];
    float4 acc = make_float4(0.f, 0.f, 0.f, 0.f);
    for (int e = beg; e < end; e++) {
        int s = g_csr_src[e];
        float4 v = *(const float4*)&X[(size_t)s * F + lane * 4];
        acc.x += v.x; acc.y += v.y; acc.z += v.z; acc.w += v.w;
    }
    float inv = g_invdeg[w];
    *(float4*)&g_agg[(size_t)w * F + lane * 4] =
        make_float4(acc.x * inv, acc.y * inv, acc.z * inv, acc.w * inv);
}

// ---- mma.sync bf16 3-term GEMM, 512 threads --------------------------------
// Y[128b x N_OUT] = [X | XN] @ split-W + bias (+relu)
template <int N_OUT, bool DUAL, bool RELU>
__global__ void __launch_bounds__(512) sage_mma(
    const float* __restrict__ X, const float* __restrict__ XN,
    const __nv_bfloat16* __restrict__ Whi,
    const __nv_bfloat16* __restrict__ Wlo,
    const float* __restrict__ bsv, const float* __restrict__ bnv,
    float* __restrict__ Y) {
    constexpr int KTOT = DUAL ? 256 : 128;
    constexpr int NCH = KTOT / 64;            // K chunks of 64
    constexpr int NWN = N_OUT / 32;           // warps along N (4 or 2)
    constexpr int NWM = 16 / NWN;             // warps along M (4 or 8)
    constexpr int MI = 128 / NWM / 16;        // m16 frags per warp (2 or 1)
    constexpr int BT = N_OUT * 128;           // bytes per B plane chunk
    constexpr int OFF_B = 65536;              // after 2 A double-buffers
    constexpr int OFF_BIAS = OFF_B + 4 * BT;

    extern __shared__ char smc[];
    const uint32_t sb = smem_u32(smc);
    const int tid = threadIdx.x, wid = tid >> 5, lane = tid & 31;
    const int node0 = blockIdx.x * 128;
    float* sB = (float*)(smc + OFF_BIAS);
    if (tid < N_OUT) sB[tid] = bsv[tid] + (DUAL ? bnv[tid] : 0.0f);

    // ---- B producer: cp.async per chunk, double-buffered ------------------
    auto cpasyncB = [&](int c) {
        const uint32_t dbase = sb + OFF_B + (c & 1) * (2 * BT);
        #pragma unroll
        for (int g = tid; g < N_OUT * 8; g += 512) {
            int n = g >> 3, kk = (g & 7) * 8;
            uint32_t doff = SWZ((uint32_t)(n * 128 + kk * 2));
            const int so = n * KTOT + c * 64 + kk;
            cp16(dbase + doff, Whi + so);
            cp16(dbase + BT + doff, Wlo + so);
        }
        CP_COMMIT;
    };
    // ---- A producer: each thread owns a quarter row (16 floats) -----------
    float4 st[4];
    const int arow = tid >> 2;
    const int acolb = (tid & 3) * 16;
    const int pnode = node0 + arow;
    auto do_ldgA = [&](int c) {
        const float* src = (DUAL && c >= 2) ? (XN + (c - 2) * 64) : (X + c * 64);
        if (pnode < N_NODES) {
            const float4* p = (const float4*)(src + (size_t)pnode * F + acolb);
            #pragma unroll
            for (int j = 0; j < 4; j++) st[j] = p[j];
        } else {
            #pragma unroll
            for (int j = 0; j < 4; j++) st[j] = make_float4(0.f, 0.f, 0.f, 0.f);
        }
    };
    auto do_stsA = [&](int b) {
        char* dhi = smc + b * 32768;
        char* dlo = dhi + 16384;
        #pragma unroll
        for (int j = 0; j < 2; j++) {
            float4 v0 = st[2 * j], v1 = st[2 * j + 1];
            uint4 H, L;
            H.x = pk_bf16(v0.x, v0.y); H.y = pk_bf16(v0.z, v0.w);
            H.z = pk_bf16(v1.x, v1.y); H.w = pk_bf16(v1.z, v1.w);
            L.x = pk_bf16(v0.x - lo_f(H.x), v0.y - hi_f(H.x));
            L.y = pk_bf16(v0.z - lo_f(H.y), v0.w - hi_f(H.y));
            L.z = pk_bf16(v1.x - lo_f(H.z), v1.y - hi_f(H.z));
            L.w = pk_bf16(v1.z - lo_f(H.w), v1.w - hi_f(H.w));
            uint32_t off = SWZ((uint32_t)(arow * 128 + (acolb + 8 * j) * 2));
            *(uint4*)(dhi + off) = H;
            *(uint4*)(dlo + off) = L;
        }
    };

    // lane-invariant ldmatrix bases
    const int wn = (wid % NWN) * 32;
    const int wm = (wid / NWN) * (MI * 16);
    const int ar = wm + (lane & 15);
    const uint32_t a_base = (uint32_t)(ar * 128 + (lane >> 4) * 16);
    const uint32_t a_mask = (uint32_t)((ar & 7) << 4);
    const int br = wn + (lane & 7) + ((lane >> 4) << 3);
    const uint32_t b_base = (uint32_t)(br * 128 + ((lane >> 3) & 1) * 16);
    const uint32_t b_mask = (uint32_t)((br & 7) << 4);

    float acc[MI][4][4];
    #pragma unroll
    for (int mi = 0; mi < MI; mi++)
        #pragma unroll
        for (int ni = 0; ni < 4; ni++)
            #pragma unroll
            for (int q = 0; q < 4; q++) acc[mi][ni][q] = 0.f;

    cpasyncB(0);
    do_ldgA(0);
    do_stsA(0);
    CP_WAIT0;
    __syncthreads();

    #pragma unroll 1
    for (int c = 0; c < NCH; c++) {
        if (c + 1 < NCH) { do_ldgA(c + 1); cpasyncB(c + 1); }
        const uint32_t ahi = sb + (c & 1) * 32768;
        const uint32_t alo = ahi + 16384;
        const uint32_t bhib = sb + OFF_B + (c & 1) * (2 * BT);
        const uint32_t blob = bhib + BT;
        #pragma unroll
        for (int ks = 0; ks < 4; ks++) {
            uint32_t ah[MI][4], al[MI][4], bh[4][2], bl[4][2];
            const uint32_t ka = (a_base + ks * 32) ^ a_mask;
            #pragma unroll
            for (int mi = 0; mi < MI; mi++) {
                ldsm4(ah[mi], ahi + ka + mi * 2048);
                ldsm4(al[mi], alo + ka + mi * 2048);
            }
            const uint32_t kb = (b_base + ks * 32) ^ b_mask;
            ldsm4(&bh[0][0], bhib + kb);
            ldsm4(&bh[2][0], bhib + kb + 2048);
            ldsm4(&bl[0][0], blob + kb);
            ldsm4(&bl[2][0], blob + kb + 2048);
            #pragma unroll
            for (int mi = 0; mi < MI; mi++)
                #pragma unroll
                for (int ni = 0; ni < 4; ni++)
                    mma16816(acc[mi][ni], ah[mi], bh[ni]);
            #pragma unroll
            for (int mi = 0; mi < MI; mi++)
                #pragma unroll
                for (int ni = 0; ni < 4; ni++)
                    mma16816(acc[mi][ni], al[mi], bh[ni]);
            #pragma unroll
            for (int mi = 0; mi < MI; mi++)
                #pragma unroll
                for (int ni = 0; ni < 4; ni++)
                    mma16816(acc[mi][ni], ah[mi], bl[ni]);
        }
        if (c + 1 < NCH) {
            do_stsA((c + 1) & 1);
            CP_WAIT0;
            __syncthreads();
        }
    }

    // ---- epilogue ----------------------------------------------------------
    const int erow = wm + (lane >> 2);
    const int ecol = wn + (lane & 3) * 2;
    #pragma unroll
    for (int mi = 0; mi < MI; mi++) {
        #pragma unroll
        for (int h = 0; h < 2; h++) {
            const int gr = node0 + erow + mi * 16 + h * 8;
            if (gr >= N_NODES) continue;
            float* yp = Y + (size_t)gr * N_OUT;
            #pragma unroll
            for (int ni = 0; ni < 4; ni++) {
                float2 o;
                o.x = acc[mi][ni][2 * h] + sB[ecol + ni * 8];
                o.y = acc[mi][ni][2 * h + 1] + sB[ecol + ni * 8 + 1];
                if (RELU) { o.x = fmaxf(o.x, 0.f); o.y = fmaxf(o.y, 0.f); }
                *(float2*)(yp + ecol + ni * 8) = o;
            }
        }
    }
}

// ---------------------------------------------------------------------------
extern "C" void kernel_launch(void* const* d_in, const int* in_sizes, int n_in,
                              void* d_out, int out_size) {
    const float* feats = (const float*)d_in[0];
    const int* src = (const int*)d_in[1];
    const int* dst = (const int*)d_in[2];
    const float* Ws[3] = {(const float*)d_in[3], (const float*)d_in[7],
                          (const float*)d_in[11]};
    const float* bs[3] = {(const float*)d_in[4], (const float*)d_in[8],
                          (const float*)d_in[12]};
    const float* Wn[3] = {(const float*)d_in[5], (const float*)d_in[9],
                          (const float*)d_in[13]};
    const float* bn[3] = {(const float*)d_in[6], (const float*)d_in[10],
                          (const float*)d_in[14]};
    const float* Wout = (const float*)d_in[15];
    const float* bout = (const float*)d_in[16];

    float *h0, *h1, *agg;
    __nv_bfloat16 *whi, *wlo;
    cudaGetSymbolAddress((void**)&h0, g_hbuf0);
    cudaGetSymbolAddress((void**)&h1, g_hbuf1);
    cudaGetSymbolAddress((void**)&agg, g_agg);
    cudaGetSymbolAddress((void**)&whi, g_whi);
    cudaGetSymbolAddress((void**)&wlo, g_wlo);

    // smem: 64KB A bufs + 4 B plane-chunks + bias
    const int SMEM_DUAL = 65536 + 4 * 128 * 128 + 512;  // 131,584
    const int SMEM_FIN = 65536 + 4 * 64 * 128 + 256;    //  98,560

    auto kRelu = sage_mma<128, true, true>;
    auto kNoRelu = sage_mma<128, true, false>;
    auto kFinal = sage_mma<64, false, false>;
    cudaFuncSetAttribute((const void*)kRelu,
                         cudaFuncAttributeMaxDynamicSharedMemorySize, SMEM_DUAL);
    cudaFuncSetAttribute((const void*)kNoRelu,
                         cudaFuncAttributeMaxDynamicSharedMemorySize, SMEM_DUAL);
    cudaFuncSetAttribute((const void*)kFinal,
                         cudaFuncAttributeMaxDynamicSharedMemorySize, SMEM_FIN);

    const int NPART = (N_NODES + 1023) / 1024;  // 98
    init_kernel<<<(N_NODES + 255) / 256, 256>>>();
    count_kernel<<<(N_EDGES + 255) / 256, 256>>>(dst);
    scanall_kernel<<<NPART, 1024>>>();
    fill_kernel<<<(N_EDGES + 255) / 256, 256>>>(src, dst);
    wconv_kernel<<<(W_TOTAL + 255) / 256, 256>>>(Ws[0], Wn[0], Ws[1], Wn[1],
                                                 Ws[2], Wn[2], Wout);

    const int AGG_BLOCKS = (N_NODES * 32 + 255) / 256;
    const int GB = (N_NODES + 127) / 128;  // 782

    agg_kernel<<<AGG_BLOCKS, 256>>>(feats);
    kRelu<<<GB, 512, SMEM_DUAL>>>(feats, agg, whi, wlo, bs[0], bn[0], h0);
    agg_kernel<<<AGG_BLOCKS, 256>>>(h0);
    kRelu<<<GB, 512, SMEM_DUAL>>>(h0, agg, whi + 32768, wlo + 32768, bs[1],
                                  bn[1], h1);
    agg_kernel<<<AGG_BLOCKS, 256>>>(h1);
    kNoRelu<<<GB, 512, SMEM_DUAL>>>(h1, agg, whi + 65536, wlo + 65536, bs[2],
                                    bn[2], h0);
    kFinal<<<GB, 512, SMEM_FIN>>>(h0, nullptr, whi + 98304, wlo + 98304, bout,
                                  nullptr, (float*)d_out);
}

// round 7
// speedup vs baseline: 1.6501x; 1.0379x over previous
#include <cuda_runtime.h>
#include <cuda_bf16.h>
#include <cstdint>
#include <cstddef>

// ---------------------------------------------------------------------------
// GraphSAGE on sm_100 (base target):
//   CSR: init+wconv -> count -> single-pass scan (cursor-seeded) -> fill
//   3x [ agg (warp/node segment-mean) ; dual GEMM mma.sync bf16 3-term ]
//   layer2 GEMM additionally fuses the final 128->64 linear in-CTA
//   (h2 never touches gmem).
//
// Dual GEMM: X*Ws + XN*Wn == [X|XN] @ [Ws;Wn] -> one GEMM, K=256.
// Precision: x = hi + lo (bf16); x*w ~ hi*whi + lo*whi + hi*wlo (3 terms).
// GEMM CTA: 512 threads (16 warps = 4/SMSP), tile 128(M) x 128(N); A chunks
// double-buffered via register-staged LDG; B chunks via cp.async.
// ---------------------------------------------------------------------------

#define N_NODES 100000
#define N_EDGES 600000
#define F 128

// ---- scratch ---------------------------------------------------------------
__device__ float g_hbuf0[(size_t)N_NODES * F];
__device__ float g_hbuf1[(size_t)N_NODES * F];
__device__ float g_agg[(size_t)N_NODES * F];
__device__ float g_invdeg[N_NODES];
__device__ int   g_deg[N_NODES];
__device__ int   g_cursor[N_NODES];
__device__ int   g_csr_off[N_NODES + 1];
__device__ int   g_csr_src[N_EDGES];
__device__ int   g_blockagg[128];
// bf16 hi/lo weights, [n][k]: layers 0..2: n 0..127, k 0..255 (k<128 self,
// else neigh); final: n 0..63, k 0..127.
#define W_TOTAL (3 * 128 * 256 + 64 * 128)
__device__ __nv_bfloat16 g_whi[W_TOTAL];
__device__ __nv_bfloat16 g_wlo[W_TOTAL];

// ---- helpers ---------------------------------------------------------------
__device__ __forceinline__ uint32_t smem_u32(const void* p) {
    uint32_t a;
    asm("{ .reg .u64 t; cvta.to.shared.u64 t, %1; cvt.u32.u64 %0, t; }"
        : "=r"(a) : "l"(p));
    return a;
}
__device__ __forceinline__ void mma16816(float* c, const uint32_t* a,
                                         const uint32_t* b) {
    asm volatile(
        "mma.sync.aligned.m16n8k16.row.col.f32.bf16.bf16.f32 "
        "{%0,%1,%2,%3}, {%4,%5,%6,%7}, {%8,%9}, {%0,%1,%2,%3};"
        : "+f"(c[0]), "+f"(c[1]), "+f"(c[2]), "+f"(c[3])
        : "r"(a[0]), "r"(a[1]), "r"(a[2]), "r"(a[3]), "r"(b[0]), "r"(b[1]));
}
__device__ __forceinline__ void ldsm4(uint32_t* r, uint32_t addr) {
    asm volatile(
        "ldmatrix.sync.aligned.m8n8.x4.shared.b16 {%0,%1,%2,%3}, [%4];"
        : "=r"(r[0]), "=r"(r[1]), "=r"(r[2]), "=r"(r[3]) : "r"(addr));
}
#define SWZ(o) ((o) ^ (((o) >> 3) & 0x70))
// pack two floats as bf16x2 (low = a, high = b)
__device__ __forceinline__ uint32_t pk_bf16(float a, float b) {
    uint32_t r;
    asm("cvt.rn.bf16x2.f32 %0, %1, %2;" : "=r"(r) : "f"(b), "f"(a));
    return r;
}
__device__ __forceinline__ float lo_f(uint32_t p) {
    return __uint_as_float(p << 16);
}
__device__ __forceinline__ float hi_f(uint32_t p) {
    return __uint_as_float(p & 0xFFFF0000u);
}
__device__ __forceinline__ void cp16(uint32_t d, const void* s) {
    asm volatile("cp.async.cg.shared.global [%0], [%1], 16;" ::"r"(d), "l"(s)
                 : "memory");
}
#define CP_COMMIT asm volatile("cp.async.commit_group;" ::: "memory")
#define CP_WAIT0 asm volatile("cp.async.wait_group 0;" ::: "memory")

// ---- init + weight pre-split (merged) --------------------------------------
__global__ void init_kernel(const float* w0s, const float* w0n,
                            const float* w1s, const float* w1n,
                            const float* w2s, const float* w2n,
                            const float* wo) {
    int i = blockIdx.x * blockDim.x + threadIdx.x;
    if (i < N_NODES) g_deg[i] = 0;
    if (i < 128) g_blockagg[i] = 0;
    if (i < W_TOTAL) {
        float w;
        if (i < 3 * 32768) {
            int l = i >> 15, local = i & 32767;
            int n = local >> 8, k = local & 255;
            const float* ws = (l == 0) ? w0s : (l == 1) ? w1s : w2s;
            const float* wn = (l == 0) ? w0n : (l == 1) ? w1n : w2n;
            w = (k < 128) ? ws[k * 128 + n] : wn[(k - 128) * 128 + n];
        } else {
            int local = i - 3 * 32768;
            int n = local >> 7, k = local & 127;
            w = wo[k * 64 + n];
        }
        __nv_bfloat16 hi = __float2bfloat16(w);
        g_whi[i] = hi;
        g_wlo[i] = __float2bfloat16(w - __bfloat162float(hi));
    }
}
__global__ void count_kernel(const int* __restrict__ dst) {
    int e = blockIdx.x * blockDim.x + threadIdx.x;
    if (e < N_EDGES) atomicAdd(&g_deg[dst[e]], 1);
}
// single-pass scan: publish block aggregate, warp-parallel lookback; seeds
// the fill cursors with the offsets.
__global__ void scanall_kernel() {
    __shared__ int ws[32];
    __shared__ int s_base;
    const int tid = threadIdx.x, lane = tid & 31, w = tid >> 5;
    const int bid = blockIdx.x;
    const int i = bid * 1024 + tid;
    const int x = (i < N_NODES) ? g_deg[i] : 0;
    int inc = x;
    #pragma unroll
    for (int o = 1; o < 32; o <<= 1) {
        int v = __shfl_up_sync(0xFFFFFFFF, inc, o);
        if (lane >= o) inc += v;
    }
    if (lane == 31) ws[w] = inc;
    __syncthreads();
    if (w == 0) {
        int s = ws[lane];
        #pragma unroll
        for (int o = 1; o < 32; o <<= 1) {
            int v = __shfl_up_sync(0xFFFFFFFF, s, o);
            if (lane >= o) s += v;
        }
        ws[lane] = s;
    }
    __syncthreads();
    const int local_excl = ((w == 0) ? 0 : ws[w - 1]) + inc - x;
    const int T = ws[31];
    if (tid == 0) atomicExch(&g_blockagg[bid], T | (1 << 30));
    if (w == 0) {
        int sum = 0;
        for (int j = lane; j < bid; j += 32) {
            int v;
            do { v = atomicAdd(&g_blockagg[j], 0); } while (v == 0);
            sum += v & 0x3FFFFFFF;
        }
        #pragma unroll
        for (int o = 16; o > 0; o >>= 1)
            sum += __shfl_down_sync(0xFFFFFFFF, sum, o);
        if (lane == 0) s_base = sum;
    }
    __syncthreads();
    if (i < N_NODES) {
        const int off = s_base + local_excl;
        g_csr_off[i] = off;
        g_cursor[i] = off;
        g_invdeg[i] = 1.0f / fmaxf((float)x, 1.0f);
    }
    if (i == 0) g_csr_off[N_NODES] = N_EDGES;
}
__global__ void fill_kernel(const int* __restrict__ src,
                            const int* __restrict__ dst) {
    int e = blockIdx.x * blockDim.x + threadIdx.x;
    if (e < N_EDGES) {
        int pos = atomicAdd(&g_cursor[dst[e]], 1);
        g_csr_src[pos] = src[e];
    }
}

// ---- aggregation: warp per node, segment mean ------------------------------
__global__ void agg_kernel(const float* __restrict__ X) {
    int w = (blockIdx.x * blockDim.x + threadIdx.x) >> 5;
    int lane = threadIdx.x & 31;
    if (w >= N_NODES) return;
    int beg = g_csr_off[w], end = g_csr_off[w + 1];
    float4 acc = make_float4(0.f, 0.f, 0.f, 0.f);
    for (int e = beg; e < end; e++) {
        int s = g_csr_src[e];
        float4 v = *(const float4*)&X[(size_t)s * F + lane * 4];
        acc.x += v.x; acc.y += v.y; acc.z += v.z; acc.w += v.w;
    }
    float inv = g_invdeg[w];
    *(float4*)&g_agg[(size_t)w * F + lane * 4] =
        make_float4(acc.x * inv, acc.y * inv, acc.z * inv, acc.w * inv);
}

// ---- mma.sync bf16 3-term GEMM, 512 threads --------------------------------
// Y[128b x 128] = [X | XN] @ split-W + bias (+relu)
// FUSE: additionally compute (Y tile) @ W_out + bout -> Yout (64 wide),
// with Y never written to gmem.
template <bool RELU, bool FUSE>
__global__ void __launch_bounds__(512) sage_mma(
    const float* __restrict__ X, const float* __restrict__ XN,
    const __nv_bfloat16* __restrict__ Whi,
    const __nv_bfloat16* __restrict__ Wlo,
    const float* __restrict__ bsv, const float* __restrict__ bnv,
    float* __restrict__ Y,
    const __nv_bfloat16* __restrict__ WOhi,
    const __nv_bfloat16* __restrict__ WOlo,
    const float* __restrict__ bout, float* __restrict__ Yout) {
    constexpr int KTOT = 256;
    constexpr int NCH = 4;                    // K chunks of 64
    constexpr int BT = 128 * 128;             // 16384 B per B plane chunk
    constexpr int OFF_B = 65536;              // after 2 A double-buffers
    constexpr int OFF_WO = OFF_B + 4 * BT;    // 131072 (FUSE only)
    constexpr int OFF_BIAS = FUSE ? (OFF_WO + 32768) : OFF_WO;

    extern __shared__ char smc[];
    const uint32_t sb = smem_u32(smc);
    const int tid = threadIdx.x, wid = tid >> 5, lane = tid & 31;
    const int node0 = blockIdx.x * 128;
    float* sB = (float*)(smc + OFF_BIAS);
    float* sBo = (float*)(smc + OFF_BIAS + 512);
    if (tid < 128) sB[tid] = bsv[tid] + bnv[tid];
    if (FUSE && tid < 64) sBo[tid] = bout[tid];

    // ---- B producer: cp.async per chunk, double-buffered ------------------
    auto cpasyncB = [&](int c) {
        const uint32_t dbase = sb + OFF_B + (c & 1) * (2 * BT);
        #pragma unroll
        for (int g = tid; g < 128 * 8; g += 512) {
            int n = g >> 3, kk = (g & 7) * 8;
            uint32_t doff = SWZ((uint32_t)(n * 128 + kk * 2));
            const int so = n * KTOT + c * 64 + kk;
            cp16(dbase + doff, Whi + so);
            cp16(dbase + BT + doff, Wlo + so);
        }
        CP_COMMIT;
    };
    // ---- A producer: each thread owns a quarter row (16 floats) -----------
    float4 st[4];
    const int arow = tid >> 2;
    const int acolb = (tid & 3) * 16;
    const int pnode = node0 + arow;
    auto do_ldgA = [&](int c) {
        const float* src = (c >= 2) ? (XN + (c - 2) * 64) : (X + c * 64);
        if (pnode < N_NODES) {
            const float4* p = (const float4*)(src + (size_t)pnode * F + acolb);
            #pragma unroll
            for (int j = 0; j < 4; j++) st[j] = p[j];
        } else {
            #pragma unroll
            for (int j = 0; j < 4; j++) st[j] = make_float4(0.f, 0.f, 0.f, 0.f);
        }
    };
    auto do_stsA = [&](int b) {
        char* dhi = smc + b * 32768;
        char* dlo = dhi + 16384;
        #pragma unroll
        for (int j = 0; j < 2; j++) {
            float4 v0 = st[2 * j], v1 = st[2 * j + 1];
            uint4 H, L;
            H.x = pk_bf16(v0.x, v0.y); H.y = pk_bf16(v0.z, v0.w);
            H.z = pk_bf16(v1.x, v1.y); H.w = pk_bf16(v1.z, v1.w);
            L.x = pk_bf16(v0.x - lo_f(H.x), v0.y - hi_f(H.x));
            L.y = pk_bf16(v0.z - lo_f(H.y), v0.w - hi_f(H.y));
            L.z = pk_bf16(v1.x - lo_f(H.z), v1.y - hi_f(H.z));
            L.w = pk_bf16(v1.z - lo_f(H.w), v1.w - hi_f(H.w));
            uint32_t off = SWZ((uint32_t)(arow * 128 + (acolb + 8 * j) * 2));
            *(uint4*)(dhi + off) = H;
            *(uint4*)(dlo + off) = L;
        }
    };

    // lane-invariant ldmatrix bases (main GEMM: 4 warps N x 4 warps M, MI=2)
    const int wn = (wid & 3) * 32;
    const int wm = (wid >> 2) * 32;
    const int ar = wm + (lane & 15);
    const uint32_t a_base = (uint32_t)(ar * 128 + (lane >> 4) * 16);
    const uint32_t a_mask = (uint32_t)((ar & 7) << 4);
    const int br = wn + (lane & 7) + ((lane >> 4) << 3);
    const uint32_t b_base = (uint32_t)(br * 128 + ((lane >> 3) & 1) * 16);
    const uint32_t b_mask = (uint32_t)((br & 7) << 4);

    float acc[2][4][4];
    #pragma unroll
    for (int mi = 0; mi < 2; mi++)
        #pragma unroll
        for (int ni = 0; ni < 4; ni++)
            #pragma unroll
            for (int q = 0; q < 4; q++) acc[mi][ni][q] = 0.f;

    // prologue: W_out (FUSE), B0, A0
    if (FUSE) {
        #pragma unroll
        for (int g = tid; g < 2048; g += 512) {
            int p = g >> 10, r = g & 1023;
            int n = r >> 4, kk = (r & 15) * 8;
            int chunk = kk >> 6, lc = kk & 63;
            uint32_t doff = (uint32_t)(OFF_WO + p * 16384 + chunk * 8192) +
                            SWZ((uint32_t)(n * 128 + lc * 2));
            cp16(sb + doff, (p ? WOlo : WOhi) + n * 128 + kk);
        }
        CP_COMMIT;
    }
    cpasyncB(0);
    do_ldgA(0);
    do_stsA(0);
    CP_WAIT0;
    __syncthreads();

    #pragma unroll 1
    for (int c = 0; c < NCH; c++) {
        if (c + 1 < NCH) { do_ldgA(c + 1); cpasyncB(c + 1); }
        const uint32_t ahi = sb + (c & 1) * 32768;
        const uint32_t alo = ahi + 16384;
        const uint32_t bhib = sb + OFF_B + (c & 1) * (2 * BT);
        const uint32_t blob = bhib + BT;
        #pragma unroll
        for (int ks = 0; ks < 4; ks++) {
            uint32_t ah[2][4], al[2][4], bh[4][2], bl[4][2];
            const uint32_t ka = (a_base + ks * 32) ^ a_mask;
            #pragma unroll
            for (int mi = 0; mi < 2; mi++) {
                ldsm4(ah[mi], ahi + ka + mi * 2048);
                ldsm4(al[mi], alo + ka + mi * 2048);
            }
            const uint32_t kb = (b_base + ks * 32) ^ b_mask;
            ldsm4(&bh[0][0], bhib + kb);
            ldsm4(&bh[2][0], bhib + kb + 2048);
            ldsm4(&bl[0][0], blob + kb);
            ldsm4(&bl[2][0], blob + kb + 2048);
            #pragma unroll
            for (int mi = 0; mi < 2; mi++)
                #pragma unroll
                for (int ni = 0; ni < 4; ni++)
                    mma16816(acc[mi][ni], ah[mi], bh[ni]);
            #pragma unroll
            for (int mi = 0; mi < 2; mi++)
                #pragma unroll
                for (int ni = 0; ni < 4; ni++)
                    mma16816(acc[mi][ni], al[mi], bh[ni]);
            #pragma unroll
            for (int mi = 0; mi < 2; mi++)
                #pragma unroll
                for (int ni = 0; ni < 4; ni++)
                    mma16816(acc[mi][ni], ah[mi], bl[ni]);
        }
        if (c + 1 < NCH) {
            do_stsA((c + 1) & 1);
            CP_WAIT0;
            __syncthreads();
        }
    }

    const int erow = wm + (lane >> 2);
    const int ecol = wn + (lane & 3) * 2;

    if (!FUSE) {
        // ---- plain epilogue ------------------------------------------------
        #pragma unroll
        for (int mi = 0; mi < 2; mi++) {
            #pragma unroll
            for (int h = 0; h < 2; h++) {
                const int gr = node0 + erow + mi * 16 + h * 8;
                if (gr >= N_NODES) continue;
                float* yp = Y + (size_t)gr * 128;
                #pragma unroll
                for (int ni = 0; ni < 4; ni++) {
                    float2 o;
                    o.x = acc[mi][ni][2 * h] + sB[ecol + ni * 8];
                    o.y = acc[mi][ni][2 * h + 1] + sB[ecol + ni * 8 + 1];
                    if (RELU) { o.x = fmaxf(o.x, 0.f); o.y = fmaxf(o.y, 0.f); }
                    *(float2*)(yp + ecol + ni * 8) = o;
                }
            }
        }
        return;
    }

    // ---- FUSE: pack h2 tile (bias added, no relu) into smem split bf16 ----
    // hi planes -> A buf0 region [0,32768); lo planes -> B buf0 region.
    // Both are dead during the last main chunk (which used the '1' buffers).
    #pragma unroll
    for (int mi = 0; mi < 2; mi++) {
        #pragma unroll
        for (int h = 0; h < 2; h++) {
            const int r = erow + mi * 16 + h * 8;
            #pragma unroll
            for (int ni = 0; ni < 4; ni++) {
                const int cc = ecol + ni * 8;
                float ox = acc[mi][ni][2 * h] + sB[cc];
                float oy = acc[mi][ni][2 * h + 1] + sB[cc + 1];
                uint32_t hi2 = pk_bf16(ox, oy);
                uint32_t lo2 = pk_bf16(ox - lo_f(hi2), oy - hi_f(hi2));
                const int chunk = cc >> 6, lc = cc & 63;
                uint32_t off = SWZ((uint32_t)(r * 128 + lc * 2));
                *(uint32_t*)(smc + chunk * 16384 + off) = hi2;
                *(uint32_t*)(smc + OFF_B + chunk * 16384 + off) = lo2;
            }
        }
    }
    __syncthreads();

    // ---- FUSE: h2 @ W_out + bout -> Yout (128 x 64, K=128) ----------------
    // 2 warps along N (32 each), 8 warps along M (16 rows each), MI=1.
    const int wn2 = (wid & 1) * 32;
    const int wm2 = (wid >> 1) * 16;
    const int ar2 = wm2 + (lane & 15);
    const uint32_t a_base2 = (uint32_t)(ar2 * 128 + (lane >> 4) * 16);
    const uint32_t a_mask2 = (uint32_t)((ar2 & 7) << 4);
    const int br2 = wn2 + (lane & 7) + ((lane >> 4) << 3);
    const uint32_t b_base2 = (uint32_t)(br2 * 128 + ((lane >> 3) & 1) * 16);
    const uint32_t b_mask2 = (uint32_t)((br2 & 7) << 4);

    float acc2[4][4];
    #pragma unroll
    for (int ni = 0; ni < 4; ni++)
        #pragma unroll
        for (int q = 0; q < 4; q++) acc2[ni][q] = 0.f;

    #pragma unroll
    for (int c = 0; c < 2; c++) {
        const uint32_t ahi = sb + c * 16384;
        const uint32_t alo = sb + OFF_B + c * 16384;
        const uint32_t bhib = sb + OFF_WO + c * 8192;
        const uint32_t blob = bhib + 16384;
        #pragma unroll
        for (int ks = 0; ks < 4; ks++) {
            uint32_t ah[4], al[4], bh[4][2], bl[4][2];
            const uint32_t ka = (a_base2 + ks * 32) ^ a_mask2;
            ldsm4(ah, ahi + ka);
            ldsm4(al, alo + ka);
            const uint32_t kb = (b_base2 + ks * 32) ^ b_mask2;
            ldsm4(&bh[0][0], bhib + kb);
            ldsm4(&bh[2][0], bhib + kb + 2048);
            ldsm4(&bl[0][0], blob + kb);
            ldsm4(&bl[2][0], blob + kb + 2048);
            #pragma unroll
            for (int ni = 0; ni < 4; ni++) mma16816(acc2[ni], ah, bh[ni]);
            #pragma unroll
            for (int ni = 0; ni < 4; ni++) mma16816(acc2[ni], al, bh[ni]);
            #pragma unroll
            for (int ni = 0; ni < 4; ni++) mma16816(acc2[ni], ah, bl[ni]);
        }
    }

    const int erow2 = wm2 + (lane >> 2);
    const int ecol2 = wn2 + (lane & 3) * 2;
    #pragma unroll
    for (int h = 0; h < 2; h++) {
        const int gr = node0 + erow2 + h * 8;
        if (gr >= N_NODES) continue;
        float* yp = Yout + (size_t)gr * 64;
        #pragma unroll
        for (int ni = 0; ni < 4; ni++) {
            float2 o;
            o.x = acc2[ni][2 * h] + sBo[ecol2 + ni * 8];
            o.y = acc2[ni][2 * h + 1] + sBo[ecol2 + ni * 8 + 1];
            *(float2*)(yp + ecol2 + ni * 8) = o;
        }
    }
}

// ---------------------------------------------------------------------------
extern "C" void kernel_launch(void* const* d_in, const int* in_sizes, int n_in,
                              void* d_out, int out_size) {
    const float* feats = (const float*)d_in[0];
    const int* src = (const int*)d_in[1];
    const int* dst = (const int*)d_in[2];
    const float* Ws[3] = {(const float*)d_in[3], (const float*)d_in[7],
                          (const float*)d_in[11]};
    const float* bs[3] = {(const float*)d_in[4], (const float*)d_in[8],
                          (const float*)d_in[12]};
    const float* Wn[3] = {(const float*)d_in[5], (const float*)d_in[9],
                          (const float*)d_in[13]};
    const float* bn[3] = {(const float*)d_in[6], (const float*)d_in[10],
                          (const float*)d_in[14]};
    const float* Wout = (const float*)d_in[15];
    const float* bout = (const float*)d_in[16];

    float *h0, *h1, *agg;
    __nv_bfloat16 *whi, *wlo;
    cudaGetSymbolAddress((void**)&h0, g_hbuf0);
    cudaGetSymbolAddress((void**)&h1, g_hbuf1);
    cudaGetSymbolAddress((void**)&agg, g_agg);
    cudaGetSymbolAddress((void**)&whi, g_whi);
    cudaGetSymbolAddress((void**)&wlo, g_wlo);

    const int SMEM_DUAL = 65536 + 4 * 128 * 128 + 1024;          // 132,096
    const int SMEM_FUSE = 65536 + 4 * 128 * 128 + 32768 + 1024;  // 164,864

    auto kRelu = sage_mma<true, false>;
    auto kFuse = sage_mma<false, true>;
    cudaFuncSetAttribute((const void*)kRelu,
                         cudaFuncAttributeMaxDynamicSharedMemorySize, SMEM_DUAL);
    cudaFuncSetAttribute((const void*)kFuse,
                         cudaFuncAttributeMaxDynamicSharedMemorySize, SMEM_FUSE);

    const int NPART = (N_NODES + 1023) / 1024;  // 98
    init_kernel<<<(W_TOTAL + 255) / 256, 256>>>(Ws[0], Wn[0], Ws[1], Wn[1],
                                                Ws[2], Wn[2], Wout);
    count_kernel<<<(N_EDGES + 255) / 256, 256>>>(dst);
    scanall_kernel<<<NPART, 1024>>>();
    fill_kernel<<<(N_EDGES + 255) / 256, 256>>>(src, dst);

    const int AGG_BLOCKS = (N_NODES * 32 + 255) / 256;
    const int GB = (N_NODES + 127) / 128;  // 782

    agg_kernel<<<AGG_BLOCKS, 256>>>(feats);
    kRelu<<<GB, 512, SMEM_DUAL>>>(feats, agg, whi, wlo, bs[0], bn[0], h0,
                                  nullptr, nullptr, nullptr, nullptr);
    agg_kernel<<<AGG_BLOCKS, 256>>>(h0);
    kRelu<<<GB, 512, SMEM_DUAL>>>(h0, agg, whi + 32768, wlo + 32768, bs[1],
                                  bn[1], h1, nullptr, nullptr, nullptr,
                                  nullptr);
    agg_kernel<<<AGG_BLOCKS, 256>>>(h1);
    kFuse<<<GB, 512, SMEM_FUSE>>>(h1, agg, whi + 65536, wlo + 65536, bs[2],
                                  bn[2], nullptr, whi + 98304, wlo + 98304,
                                  bout, (float*)d_out);
}

// round 8
// speedup vs baseline: 1.7964x; 1.0887x over previous
#include <cuda_runtime.h>
#include <cuda_fp16.h>
#include <cstdint>
#include <cstddef>

// ---------------------------------------------------------------------------
// GraphSAGE on sm_100 (base target):
//   CSR: init+wconv -> count -> single-pass scan (cursor-seeded) -> fill
//   3x [ agg (warp/node segment-mean) ; dual GEMM mma.sync fp16 2-term ]
//   layer2 GEMM fuses the final 128->64 linear in-CTA (h2 never in gmem).
//
// Dual GEMM: X*Ws + XN*Wn == [X|XN] @ [Ws;Wn] -> one GEMM, K=256.
// Precision: A split x = hi_f16 + lo_f16 (exact to 2^-21); W single fp16.
// Only error source = fp16 rounding of W (~2e-4 RMS, deterministic inputs).
// GEMM CTA: 512 threads (16 warps = 4/SMSP), tile 128(M) x 128(N); A chunks
// double-buffered via register-staged LDG; B chunks via cp.async.
// ---------------------------------------------------------------------------

#define N_NODES 100000
#define N_EDGES 600000
#define F 128

// ---- scratch ---------------------------------------------------------------
__device__ float g_hbuf0[(size_t)N_NODES * F];
__device__ float g_hbuf1[(size_t)N_NODES * F];
__device__ float g_agg[(size_t)N_NODES * F];
__device__ float g_invdeg[N_NODES];
__device__ int   g_deg[N_NODES];
__device__ int   g_cursor[N_NODES];
__device__ int   g_csr_off[N_NODES + 1];
__device__ int   g_csr_src[N_EDGES];
__device__ int   g_blockagg[128];
// fp16 weights, [n][k]: layers 0..2: n 0..127, k 0..255 (k<128 self, else
// neigh); final: n 0..63, k 0..127.
#define W_TOTAL (3 * 128 * 256 + 64 * 128)
__device__ __half g_wh[W_TOTAL];

// ---- helpers ---------------------------------------------------------------
__device__ __forceinline__ uint32_t smem_u32(const void* p) {
    uint32_t a;
    asm("{ .reg .u64 t; cvta.to.shared.u64 t, %1; cvt.u32.u64 %0, t; }"
        : "=r"(a) : "l"(p));
    return a;
}
__device__ __forceinline__ void mma16816(float* c, const uint32_t* a,
                                         const uint32_t* b) {
    asm volatile(
        "mma.sync.aligned.m16n8k16.row.col.f32.f16.f16.f32 "
        "{%0,%1,%2,%3}, {%4,%5,%6,%7}, {%8,%9}, {%0,%1,%2,%3};"
        : "+f"(c[0]), "+f"(c[1]), "+f"(c[2]), "+f"(c[3])
        : "r"(a[0]), "r"(a[1]), "r"(a[2]), "r"(a[3]), "r"(b[0]), "r"(b[1]));
}
__device__ __forceinline__ void ldsm4(uint32_t* r, uint32_t addr) {
    asm volatile(
        "ldmatrix.sync.aligned.m8n8.x4.shared.b16 {%0,%1,%2,%3}, [%4];"
        : "=r"(r[0]), "=r"(r[1]), "=r"(r[2]), "=r"(r[3]) : "r"(addr));
}
#define SWZ(o) ((o) ^ (((o) >> 3) & 0x70))
// pack two floats as fp16x2 (low = a, high = b)
__device__ __forceinline__ uint32_t pk_h(float a, float b) {
    __half2 h = __floats2half2_rn(a, b);
    return *(uint32_t*)&h;
}
__device__ __forceinline__ float2 up_h(uint32_t p) {
    return __half22float2(*(__half2*)&p);
}
__device__ __forceinline__ void cp16(uint32_t d, const void* s) {
    asm volatile("cp.async.cg.shared.global [%0], [%1], 16;" ::"r"(d), "l"(s)
                 : "memory");
}
#define CP_COMMIT asm volatile("cp.async.commit_group;" ::: "memory")
#define CP_WAIT0 asm volatile("cp.async.wait_group 0;" ::: "memory")

// ---- init + weight fp16 conversion (merged) --------------------------------
__global__ void init_kernel(const float* w0s, const float* w0n,
                            const float* w1s, const float* w1n,
                            const float* w2s, const float* w2n,
                            const float* wo) {
    int i = blockIdx.x * blockDim.x + threadIdx.x;
    if (i < N_NODES) g_deg[i] = 0;
    if (i < 128) g_blockagg[i] = 0;
    if (i < W_TOTAL) {
        float w;
        if (i < 3 * 32768) {
            int l = i >> 15, local = i & 32767;
            int n = local >> 8, k = local & 255;
            const float* ws = (l == 0) ? w0s : (l == 1) ? w1s : w2s;
            const float* wn = (l == 0) ? w0n : (l == 1) ? w1n : w2n;
            w = (k < 128) ? ws[k * 128 + n] : wn[(k - 128) * 128 + n];
        } else {
            int local = i - 3 * 32768;
            int n = local >> 7, k = local & 127;
            w = wo[k * 64 + n];
        }
        g_wh[i] = __float2half_rn(w);
    }
}
__global__ void count_kernel(const int* __restrict__ dst) {
    int e = blockIdx.x * blockDim.x + threadIdx.x;
    if (e < N_EDGES) atomicAdd(&g_deg[dst[e]], 1);
}
// single-pass scan: publish block aggregate, warp-parallel lookback; seeds
// the fill cursors with the offsets.
__global__ void scanall_kernel() {
    __shared__ int ws[32];
    __shared__ int s_base;
    const int tid = threadIdx.x, lane = tid & 31, w = tid >> 5;
    const int bid = blockIdx.x;
    const int i = bid * 1024 + tid;
    const int x = (i < N_NODES) ? g_deg[i] : 0;
    int inc = x;
    #pragma unroll
    for (int o = 1; o < 32; o <<= 1) {
        int v = __shfl_up_sync(0xFFFFFFFF, inc, o);
        if (lane >= o) inc += v;
    }
    if (lane == 31) ws[w] = inc;
    __syncthreads();
    if (w == 0) {
        int s = ws[lane];
        #pragma unroll
        for (int o = 1; o < 32; o <<= 1) {
            int v = __shfl_up_sync(0xFFFFFFFF, s, o);
            if (lane >= o) s += v;
        }
        ws[lane] = s;
    }
    __syncthreads();
    const int local_excl = ((w == 0) ? 0 : ws[w - 1]) + inc - x;
    const int T = ws[31];
    if (tid == 0) atomicExch(&g_blockagg[bid], T | (1 << 30));
    if (w == 0) {
        int sum = 0;
        for (int j = lane; j < bid; j += 32) {
            int v;
            do { v = atomicAdd(&g_blockagg[j], 0); } while (v == 0);
            sum += v & 0x3FFFFFFF;
        }
        #pragma unroll
        for (int o = 16; o > 0; o >>= 1)
            sum += __shfl_down_sync(0xFFFFFFFF, sum, o);
        if (lane == 0) s_base = sum;
    }
    __syncthreads();
    if (i < N_NODES) {
        const int off = s_base + local_excl;
        g_csr_off[i] = off;
        g_cursor[i] = off;
        g_invdeg[i] = 1.0f / fmaxf((float)x, 1.0f);
    }
    if (i == 0) g_csr_off[N_NODES] = N_EDGES;
}
__global__ void fill_kernel(const int* __restrict__ src,
                            const int* __restrict__ dst) {
    int e = blockIdx.x * blockDim.x + threadIdx.x;
    if (e < N_EDGES) {
        int pos = atomicAdd(&g_cursor[dst[e]], 1);
        g_csr_src[pos] = src[e];
    }
}

// ---- aggregation: warp per node, segment mean ------------------------------
__global__ void agg_kernel(const float* __restrict__ X) {
    int w = (blockIdx.x * blockDim.x + threadIdx.x) >> 5;
    int lane = threadIdx.x & 31;
    if (w >= N_NODES) return;
    int beg = g_csr_off[w], end = g_csr_off[w + 1];
    float4 acc = make_float4(0.f, 0.f, 0.f, 0.f);
    for (int e = beg; e < end; e++) {
        int s = g_csr_src[e];
        float4 v = *(const float4*)&X[(size_t)s * F + lane * 4];
        acc.x += v.x; acc.y += v.y; acc.z += v.z; acc.w += v.w;
    }
    float inv = g_invdeg[w];
    *(float4*)&g_agg[(size_t)w * F + lane * 4] =
        make_float4(acc.x * inv, acc.y * inv, acc.z * inv, acc.w * inv);
}

// ---- mma.sync fp16 2-term GEMM, 512 threads --------------------------------
// Y[128b x 128] = [X | XN] @ W_f16 + bias (+relu), A split hi+lo fp16.
// FUSE: additionally (Y tile) @ W_out + bout -> Yout (64 wide), Y not stored.
template <bool RELU, bool FUSE>
__global__ void __launch_bounds__(512) sage_mma(
    const float* __restrict__ X, const float* __restrict__ XN,
    const __half* __restrict__ Wh,
    const float* __restrict__ bsv, const float* __restrict__ bnv,
    float* __restrict__ Y,
    const __half* __restrict__ WOh,
    const float* __restrict__ bout, float* __restrict__ Yout) {
    constexpr int KTOT = 256;
    constexpr int NCH = 4;                    // K chunks of 64
    constexpr int BT = 128 * 128;             // 16384 B per B chunk (1 plane)
    constexpr int OFF_B = 65536;              // after 2 A double-buffers
    constexpr int OFF_WO = OFF_B + 2 * BT;    // 98304 (FUSE only)
    constexpr int OFF_BIAS = FUSE ? (OFF_WO + 16384) : OFF_WO;

    extern __shared__ char smc[];
    const uint32_t sb = smem_u32(smc);
    const int tid = threadIdx.x, wid = tid >> 5, lane = tid & 31;
    const int node0 = blockIdx.x * 128;
    float* sB = (float*)(smc + OFF_BIAS);
    float* sBo = (float*)(smc + OFF_BIAS + 512);
    if (tid < 128) sB[tid] = bsv[tid] + bnv[tid];
    if (FUSE && tid < 64) sBo[tid] = bout[tid];

    // ---- B producer: cp.async per chunk, double-buffered ------------------
    auto cpasyncB = [&](int c) {
        const uint32_t dbase = sb + OFF_B + (c & 1) * BT;
        #pragma unroll
        for (int g = tid; g < 128 * 8; g += 512) {
            int n = g >> 3, kk = (g & 7) * 8;
            uint32_t doff = SWZ((uint32_t)(n * 128 + kk * 2));
            cp16(dbase + doff, Wh + n * KTOT + c * 64 + kk);
        }
        CP_COMMIT;
    };
    // ---- A producer: each thread owns a quarter row (16 floats) -----------
    float4 st[4];
    const int arow = tid >> 2;
    const int acolb = (tid & 3) * 16;
    const int pnode = node0 + arow;
    auto do_ldgA = [&](int c) {
        const float* src = (c >= 2) ? (XN + (c - 2) * 64) : (X + c * 64);
        if (pnode < N_NODES) {
            const float4* p = (const float4*)(src + (size_t)pnode * F + acolb);
            #pragma unroll
            for (int j = 0; j < 4; j++) st[j] = p[j];
        } else {
            #pragma unroll
            for (int j = 0; j < 4; j++) st[j] = make_float4(0.f, 0.f, 0.f, 0.f);
        }
    };
    auto do_stsA = [&](int b) {
        char* dhi = smc + b * 32768;
        char* dlo = dhi + 16384;
        #pragma unroll
        for (int j = 0; j < 2; j++) {
            float4 v0 = st[2 * j], v1 = st[2 * j + 1];
            uint4 H, L;
            H.x = pk_h(v0.x, v0.y); H.y = pk_h(v0.z, v0.w);
            H.z = pk_h(v1.x, v1.y); H.w = pk_h(v1.z, v1.w);
            float2 f0 = up_h(H.x), f1 = up_h(H.y);
            float2 f2 = up_h(H.z), f3 = up_h(H.w);
            L.x = pk_h(v0.x - f0.x, v0.y - f0.y);
            L.y = pk_h(v0.z - f1.x, v0.w - f1.y);
            L.z = pk_h(v1.x - f2.x, v1.y - f2.y);
            L.w = pk_h(v1.z - f3.x, v1.w - f3.y);
            uint32_t off = SWZ((uint32_t)(arow * 128 + (acolb + 8 * j) * 2));
            *(uint4*)(dhi + off) = H;
            *(uint4*)(dlo + off) = L;
        }
    };

    // lane-invariant ldmatrix bases (main GEMM: 4 warps N x 4 warps M, MI=2)
    const int wn = (wid & 3) * 32;
    const int wm = (wid >> 2) * 32;
    const int ar = wm + (lane & 15);
    const uint32_t a_base = (uint32_t)(ar * 128 + (lane >> 4) * 16);
    const uint32_t a_mask = (uint32_t)((ar & 7) << 4);
    const int br = wn + (lane & 7) + ((lane >> 4) << 3);
    const uint32_t b_base = (uint32_t)(br * 128 + ((lane >> 3) & 1) * 16);
    const uint32_t b_mask = (uint32_t)((br & 7) << 4);

    float acc[2][4][4];
    #pragma unroll
    for (int mi = 0; mi < 2; mi++)
        #pragma unroll
        for (int ni = 0; ni < 4; ni++)
            #pragma unroll
            for (int q = 0; q < 4; q++) acc[mi][ni][q] = 0.f;

    // prologue: W_out (FUSE), B0, A0
    if (FUSE) {
        #pragma unroll
        for (int g = tid; g < 1024; g += 512) {
            int n = g >> 4, kk = (g & 15) * 8;
            int chunk = kk >> 6, lc = kk & 63;
            uint32_t doff = (uint32_t)(OFF_WO + chunk * 8192) +
                            SWZ((uint32_t)(n * 128 + lc * 2));
            cp16(sb + doff, WOh + n * 128 + kk);
        }
        CP_COMMIT;
    }
    cpasyncB(0);
    do_ldgA(0);
    do_stsA(0);
    CP_WAIT0;
    __syncthreads();

    #pragma unroll 1
    for (int c = 0; c < NCH; c++) {
        if (c + 1 < NCH) { do_ldgA(c + 1); cpasyncB(c + 1); }
        const uint32_t ahi = sb + (c & 1) * 32768;
        const uint32_t alo = ahi + 16384;
        const uint32_t bhib = sb + OFF_B + (c & 1) * BT;
        #pragma unroll
        for (int ks = 0; ks < 4; ks++) {
            uint32_t ah[2][4], al[2][4], bh[4][2];
            const uint32_t ka = (a_base + ks * 32) ^ a_mask;
            #pragma unroll
            for (int mi = 0; mi < 2; mi++) {
                ldsm4(ah[mi], ahi + ka + mi * 2048);
                ldsm4(al[mi], alo + ka + mi * 2048);
            }
            const uint32_t kb = (b_base + ks * 32) ^ b_mask;
            ldsm4(&bh[0][0], bhib + kb);
            ldsm4(&bh[2][0], bhib + kb + 2048);
            #pragma unroll
            for (int mi = 0; mi < 2; mi++)
                #pragma unroll
                for (int ni = 0; ni < 4; ni++)
                    mma16816(acc[mi][ni], ah[mi], bh[ni]);
            #pragma unroll
            for (int mi = 0; mi < 2; mi++)
                #pragma unroll
                for (int ni = 0; ni < 4; ni++)
                    mma16816(acc[mi][ni], al[mi], bh[ni]);
        }
        if (c + 1 < NCH) {
            do_stsA((c + 1) & 1);
            CP_WAIT0;
            __syncthreads();
        }
    }

    const int erow = wm + (lane >> 2);
    const int ecol = wn + (lane & 3) * 2;

    if (!FUSE) {
        // ---- plain epilogue ------------------------------------------------
        #pragma unroll
        for (int mi = 0; mi < 2; mi++) {
            #pragma unroll
            for (int h = 0; h < 2; h++) {
                const int gr = node0 + erow + mi * 16 + h * 8;
                if (gr >= N_NODES) continue;
                float* yp = Y + (size_t)gr * 128;
                #pragma unroll
                for (int ni = 0; ni < 4; ni++) {
                    float2 o;
                    o.x = acc[mi][ni][2 * h] + sB[ecol + ni * 8];
                    o.y = acc[mi][ni][2 * h + 1] + sB[ecol + ni * 8 + 1];
                    if (RELU) { o.x = fmaxf(o.x, 0.f); o.y = fmaxf(o.y, 0.f); }
                    *(float2*)(yp + ecol + ni * 8) = o;
                }
            }
        }
        return;
    }

    // ---- FUSE: pack h2 tile (bias, no relu) into smem split fp16 ----------
    // All main-loop buffers are dead now; hi planes -> [0,32KB), lo -> [32,64KB).
    __syncthreads();
    #pragma unroll
    for (int mi = 0; mi < 2; mi++) {
        #pragma unroll
        for (int h = 0; h < 2; h++) {
            const int r = erow + mi * 16 + h * 8;
            #pragma unroll
            for (int ni = 0; ni < 4; ni++) {
                const int cc = ecol + ni * 8;
                float ox = acc[mi][ni][2 * h] + sB[cc];
                float oy = acc[mi][ni][2 * h + 1] + sB[cc + 1];
                uint32_t hi2 = pk_h(ox, oy);
                float2 f = up_h(hi2);
                uint32_t lo2 = pk_h(ox - f.x, oy - f.y);
                const int chunk = cc >> 6, lc = cc & 63;
                uint32_t off = SWZ((uint32_t)(r * 128 + lc * 2));
                *(uint32_t*)(smc + chunk * 16384 + off) = hi2;
                *(uint32_t*)(smc + 32768 + chunk * 16384 + off) = lo2;
            }
        }
    }
    __syncthreads();

    // ---- FUSE: h2 @ W_out + bout -> Yout (128 x 64, K=128) ----------------
    // 2 warps along N (32 each), 8 warps along M (16 rows each), MI=1.
    const int wn2 = (wid & 1) * 32;
    const int wm2 = (wid >> 1) * 16;
    const int ar2 = wm2 + (lane & 15);
    const uint32_t a_base2 = (uint32_t)(ar2 * 128 + (lane >> 4) * 16);
    const uint32_t a_mask2 = (uint32_t)((ar2 & 7) << 4);
    const int br2 = wn2 + (lane & 7) + ((lane >> 4) << 3);
    const uint32_t b_base2 = (uint32_t)(br2 * 128 + ((lane >> 3) & 1) * 16);
    const uint32_t b_mask2 = (uint32_t)((br2 & 7) << 4);

    float acc2[4][4];
    #pragma unroll
    for (int ni = 0; ni < 4; ni++)
        #pragma unroll
        for (int q = 0; q < 4; q++) acc2[ni][q] = 0.f;

    #pragma unroll
    for (int c = 0; c < 2; c++) {
        const uint32_t ahi = sb + c * 16384;
        const uint32_t alo = sb + 32768 + c * 16384;
        const uint32_t bhib = sb + OFF_WO + c * 8192;
        #pragma unroll
        for (int ks = 0; ks < 4; ks++) {
            uint32_t ah[4], al[4], bh[4][2];
            const uint32_t ka = (a_base2 + ks * 32) ^ a_mask2;
            ldsm4(ah, ahi + ka);
            ldsm4(al, alo + ka);
            const uint32_t kb = (b_base2 + ks * 32) ^ b_mask2;
            ldsm4(&bh[0][0], bhib + kb);
            ldsm4(&bh[2][0], bhib + kb + 2048);
            #pragma unroll
            for (int ni = 0; ni < 4; ni++) mma16816(acc2[ni], ah, bh[ni]);
            #pragma unroll
            for (int ni = 0; ni < 4; ni++) mma16816(acc2[ni], al, bh[ni]);
        }
    }

    const int erow2 = wm2 + (lane >> 2);
    const int ecol2 = wn2 + (lane & 3) * 2;
    #pragma unroll
    for (int h = 0; h < 2; h++) {
        const int gr = node0 + erow2 + h * 8;
        if (gr >= N_NODES) continue;
        float* yp = Yout + (size_t)gr * 64;
        #pragma unroll
        for (int ni = 0; ni < 4; ni++) {
            float2 o;
            o.x = acc2[ni][2 * h] + sBo[ecol2 + ni * 8];
            o.y = acc2[ni][2 * h + 1] + sBo[ecol2 + ni * 8 + 1];
            *(float2*)(yp + ecol2 + ni * 8) = o;
        }
    }
}

// ---------------------------------------------------------------------------
extern "C" void kernel_launch(void* const* d_in, const int* in_sizes, int n_in,
                              void* d_out, int out_size) {
    const float* feats = (const float*)d_in[0];
    const int* src = (const int*)d_in[1];
    const int* dst = (const int*)d_in[2];
    const float* Ws[3] = {(const float*)d_in[3], (const float*)d_in[7],
                          (const float*)d_in[11]};
    const float* bs[3] = {(const float*)d_in[4], (const float*)d_in[8],
                          (const float*)d_in[12]};
    const float* Wn[3] = {(const float*)d_in[5], (const float*)d_in[9],
                          (const float*)d_in[13]};
    const float* bn[3] = {(const float*)d_in[6], (const float*)d_in[10],
                          (const float*)d_in[14]};
    const float* Wout = (const float*)d_in[15];
    const float* bout = (const float*)d_in[16];

    float *h0, *h1, *agg;
    __half* wh;
    cudaGetSymbolAddress((void**)&h0, g_hbuf0);
    cudaGetSymbolAddress((void**)&h1, g_hbuf1);
    cudaGetSymbolAddress((void**)&agg, g_agg);
    cudaGetSymbolAddress((void**)&wh, g_wh);

    const int SMEM_DUAL = 65536 + 2 * 128 * 128 + 1024;          //  99,328
    const int SMEM_FUSE = 65536 + 2 * 128 * 128 + 16384 + 1024;  // 115,712

    auto kRelu = sage_mma<true, false>;
    auto kFuse = sage_mma<false, true>;
    cudaFuncSetAttribute((const void*)kRelu,
                         cudaFuncAttributeMaxDynamicSharedMemorySize, SMEM_DUAL);
    cudaFuncSetAttribute((const void*)kFuse,
                         cudaFuncAttributeMaxDynamicSharedMemorySize, SMEM_FUSE);

    const int NPART = (N_NODES + 1023) / 1024;  // 98
    init_kernel<<<(W_TOTAL + 255) / 256, 256>>>(Ws[0], Wn[0], Ws[1], Wn[1],
                                                Ws[2], Wn[2], Wout);
    count_kernel<<<(N_EDGES + 255) / 256, 256>>>(dst);
    scanall_kernel<<<NPART, 1024>>>();
    fill_kernel<<<(N_EDGES + 255) / 256, 256>>>(src, dst);

    const int AGG_BLOCKS = (N_NODES * 32 + 255) / 256;
    const int GB = (N_NODES + 127) / 128;  // 782

    agg_kernel<<<AGG_BLOCKS, 256>>>(feats);
    kRelu<<<GB, 512, SMEM_DUAL>>>(feats, agg, wh, bs[0], bn[0], h0, nullptr,
                                  nullptr, nullptr);
    agg_kernel<<<AGG_BLOCKS, 256>>>(h0);
    kRelu<<<GB, 512, SMEM_DUAL>>>(h0, agg, wh + 32768, bs[1], bn[1], h1,
                                  nullptr, nullptr, nullptr);
    agg_kernel<<<AGG_BLOCKS, 256>>>(h1);
    kFuse<<<GB, 512, SMEM_FUSE>>>(h1, agg, wh + 65536, bs[2], bn[2], nullptr,
                                  wh + 98304, bout, (float*)d_out);
}

// round 9
// speedup vs baseline: 1.9759x; 1.0999x over previous
#include <cuda_runtime.h>
#include <cuda_fp16.h>
#include <cstdint>
#include <cstddef>

// ---------------------------------------------------------------------------
// GraphSAGE on sm_100 (base target):
//   CSR: init+wconv -> count -> single-pass scan -> fill ; featconv
//   3x [ agg (gather hi/lo planes, mean, re-split) ; dual GEMM fp16 2-term ]
//   layer2 GEMM fuses the final 128->64 linear in-CTA.
//
// All activations live in gmem as PRE-SPLIT fp16 hi/lo planes [node][k]:
//   x = hi + lo exactly (to 2^-21).  GEMMs stream A (hi,lo) and B via a
//   2-deep cp.async pipeline -> inner loop is pure ldsm+HMMA.
// Only error source: fp16 rounding of W (~2e-4 RMS, deterministic inputs).
// ---------------------------------------------------------------------------

#define N_NODES 100000
#define N_EDGES 600000
#define F 128
#define PLANE ((size_t)(N_NODES + 128) * F)  // padded so GEMM tiles never OOB

// ---- scratch ---------------------------------------------------------------
__device__ __half g_fhi[PLANE], g_flo[PLANE];    // split features
__device__ __half g_h0hi[PLANE], g_h0lo[PLANE];  // split h (ping)
__device__ __half g_h1hi[PLANE], g_h1lo[PLANE];  // split h (pong)
__device__ __half g_ahi[PLANE], g_alo[PLANE];    // split neighbor means
__device__ float g_invdeg[N_NODES];
__device__ int   g_deg[N_NODES];
__device__ int   g_cursor[N_NODES];
__device__ int   g_csr_off[N_NODES + 1];
__device__ int   g_csr_src[N_EDGES];
__device__ int   g_blockagg[128];
// fp16 weights, [n][k]: layers 0..2: n 0..127, k 0..255 (k<128 self, else
// neigh); final: n 0..63, k 0..127.
#define W_TOTAL (3 * 128 * 256 + 64 * 128)
__device__ __half g_wh[W_TOTAL];

// ---- helpers ---------------------------------------------------------------
__device__ __forceinline__ uint32_t smem_u32(const void* p) {
    uint32_t a;
    asm("{ .reg .u64 t; cvta.to.shared.u64 t, %1; cvt.u32.u64 %0, t; }"
        : "=r"(a) : "l"(p));
    return a;
}
__device__ __forceinline__ void mma16816(float* c, const uint32_t* a,
                                         const uint32_t* b) {
    asm volatile(
        "mma.sync.aligned.m16n8k16.row.col.f32.f16.f16.f32 "
        "{%0,%1,%2,%3}, {%4,%5,%6,%7}, {%8,%9}, {%0,%1,%2,%3};"
        : "+f"(c[0]), "+f"(c[1]), "+f"(c[2]), "+f"(c[3])
        : "r"(a[0]), "r"(a[1]), "r"(a[2]), "r"(a[3]), "r"(b[0]), "r"(b[1]));
}
__device__ __forceinline__ void ldsm4(uint32_t* r, uint32_t addr) {
    asm volatile(
        "ldmatrix.sync.aligned.m8n8.x4.shared.b16 {%0,%1,%2,%3}, [%4];"
        : "=r"(r[0]), "=r"(r[1]), "=r"(r[2]), "=r"(r[3]) : "r"(addr));
}
#define SWZ(o) ((o) ^ (((o) >> 3) & 0x70))
// pack two floats as fp16x2 (low = a, high = b)
__device__ __forceinline__ uint32_t pk_h(float a, float b) {
    __half2 h = __floats2half2_rn(a, b);
    return *(uint32_t*)&h;
}
__device__ __forceinline__ float2 up_h(uint32_t p) {
    return __half22float2(*(__half2*)&p);
}
__device__ __forceinline__ void cp16(uint32_t d, const void* s) {
    asm volatile("cp.async.cg.shared.global [%0], [%1], 16;" ::"r"(d), "l"(s)
                 : "memory");
}
#define CP_COMMIT asm volatile("cp.async.commit_group;" ::: "memory")
#define CP_WAIT(n) asm volatile("cp.async.wait_group %0;" ::"n"(n) : "memory")

// ---- init + weight fp16 conversion (merged) --------------------------------
__global__ void init_kernel(const float* w0s, const float* w0n,
                            const float* w1s, const float* w1n,
                            const float* w2s, const float* w2n,
                            const float* wo) {
    int i = blockIdx.x * blockDim.x + threadIdx.x;
    if (i < N_NODES) g_deg[i] = 0;
    if (i < 128) g_blockagg[i] = 0;
    if (i < W_TOTAL) {
        float w;
        if (i < 3 * 32768) {
            int l = i >> 15, local = i & 32767;
            int n = local >> 8, k = local & 255;
            const float* ws = (l == 0) ? w0s : (l == 1) ? w1s : w2s;
            const float* wn = (l == 0) ? w0n : (l == 1) ? w1n : w2n;
            w = (k < 128) ? ws[k * 128 + n] : wn[(k - 128) * 128 + n];
        } else {
            int local = i - 3 * 32768;
            int n = local >> 7, k = local & 127;
            w = wo[k * 64 + n];
        }
        g_wh[i] = __float2half_rn(w);
    }
}
// split features fp32 -> hi/lo fp16 planes
__global__ void featconv_kernel(const float* __restrict__ X) {
    int i = blockIdx.x * blockDim.x + threadIdx.x;  // one float4 per thread
    if (i >= N_NODES * (F / 4)) return;
    float4 v = ((const float4*)X)[i];
    uint32_t H0 = pk_h(v.x, v.y), H1 = pk_h(v.z, v.w);
    float2 f0 = up_h(H0), f1 = up_h(H1);
    uint32_t L0 = pk_h(v.x - f0.x, v.y - f0.y);
    uint32_t L1 = pk_h(v.z - f1.x, v.w - f1.y);
    ((uint2*)g_fhi)[i] = make_uint2(H0, H1);
    ((uint2*)g_flo)[i] = make_uint2(L0, L1);
}
__global__ void count_kernel(const int* __restrict__ dst) {
    int e = blockIdx.x * blockDim.x + threadIdx.x;
    if (e < N_EDGES) atomicAdd(&g_deg[dst[e]], 1);
}
// single-pass scan: publish block aggregate, warp-parallel lookback; seeds
// the fill cursors with the offsets.
__global__ void scanall_kernel() {
    __shared__ int ws[32];
    __shared__ int s_base;
    const int tid = threadIdx.x, lane = tid & 31, w = tid >> 5;
    const int bid = blockIdx.x;
    const int i = bid * 1024 + tid;
    const int x = (i < N_NODES) ? g_deg[i] : 0;
    int inc = x;
    #pragma unroll
    for (int o = 1; o < 32; o <<= 1) {
        int v = __shfl_up_sync(0xFFFFFFFF, inc, o);
        if (lane >= o) inc += v;
    }
    if (lane == 31) ws[w] = inc;
    __syncthreads();
    if (w == 0) {
        int s = ws[lane];
        #pragma unroll
        for (int o = 1; o < 32; o <<= 1) {
            int v = __shfl_up_sync(0xFFFFFFFF, s, o);
            if (lane >= o) s += v;
        }
        ws[lane] = s;
    }
    __syncthreads();
    const int local_excl = ((w == 0) ? 0 : ws[w - 1]) + inc - x;
    const int T = ws[31];
    if (tid == 0) atomicExch(&g_blockagg[bid], T | (1 << 30));
    if (w == 0) {
        int sum = 0;
        for (int j = lane; j < bid; j += 32) {
            int v;
            do { v = atomicAdd(&g_blockagg[j], 0); } while (v == 0);
            sum += v & 0x3FFFFFFF;
        }
        #pragma unroll
        for (int o = 16; o > 0; o >>= 1)
            sum += __shfl_down_sync(0xFFFFFFFF, sum, o);
        if (lane == 0) s_base = sum;
    }
    __syncthreads();
    if (i < N_NODES) {
        const int off = s_base + local_excl;
        g_csr_off[i] = off;
        g_cursor[i] = off;
        g_invdeg[i] = 1.0f / fmaxf((float)x, 1.0f);
    }
    if (i == 0) g_csr_off[N_NODES] = N_EDGES;
}
__global__ void fill_kernel(const int* __restrict__ src,
                            const int* __restrict__ dst) {
    int e = blockIdx.x * blockDim.x + threadIdx.x;
    if (e < N_EDGES) {
        int pos = atomicAdd(&g_cursor[dst[e]], 1);
        g_csr_src[pos] = src[e];
    }
}

// ---- aggregation: warp per node; gather hi/lo planes, mean, re-split -------
__global__ void agg_kernel(const __half* __restrict__ Xhi,
                           const __half* __restrict__ Xlo) {
    int w = (blockIdx.x * blockDim.x + threadIdx.x) >> 5;
    int lane = threadIdx.x & 31;
    if (w >= N_NODES) return;
    int beg = g_csr_off[w], end = g_csr_off[w + 1];
    float4 acc = make_float4(0.f, 0.f, 0.f, 0.f);
    for (int e = beg; e < end; e++) {
        int s = g_csr_src[e];
        size_t base = (size_t)s * F + lane * 4;
        uint2 h2 = *(const uint2*)(Xhi + base);
        uint2 l2 = *(const uint2*)(Xlo + base);
        float2 a = up_h(h2.x), b = up_h(h2.y);
        float2 c = up_h(l2.x), d = up_h(l2.y);
        acc.x += a.x + c.x; acc.y += a.y + c.y;
        acc.z += b.x + d.x; acc.w += b.y + d.y;
    }
    float inv = g_invdeg[w];
    float vx = acc.x * inv, vy = acc.y * inv;
    float vz = acc.z * inv, vw = acc.w * inv;
    uint32_t H0 = pk_h(vx, vy), H1 = pk_h(vz, vw);
    float2 f0 = up_h(H0), f1 = up_h(H1);
    uint32_t L0 = pk_h(vx - f0.x, vy - f0.y);
    uint32_t L1 = pk_h(vz - f1.x, vw - f1.y);
    size_t ob = (size_t)w * F + lane * 4;
    *(uint2*)(g_ahi + ob) = make_uint2(H0, H1);
    *(uint2*)(g_alo + ob) = make_uint2(L0, L1);
}

// ---- all-cp.async fp16 2-term GEMM, 512 threads -----------------------------
// Y = [self | agg] @ W_f16 + bias (+relu); A pre-split hi/lo planes.
// FUSE: (Y tile) @ W_out + bout -> Yout (64 wide), Y not stored.
template <bool RELU, bool FUSE>
__global__ void __launch_bounds__(512) sage_mma(
    const __half* __restrict__ Shi, const __half* __restrict__ Slo,
    const __half* __restrict__ Nhi, const __half* __restrict__ Nlo,
    const __half* __restrict__ Wh,
    const float* __restrict__ bsv, const float* __restrict__ bnv,
    __half* __restrict__ Yhi, __half* __restrict__ Ylo,
    const __half* __restrict__ WOh,
    const float* __restrict__ bout, float* __restrict__ Yout) {
    constexpr int OFF_B = 65536;              // after 2 A bufs (hi+lo = 32KB)
    constexpr int OFF_WO = OFF_B + 32768;     // 98304 (FUSE only)
    constexpr int OFF_BIAS = FUSE ? (OFF_WO + 16384) : OFF_WO;

    extern __shared__ char smc[];
    const uint32_t sb = smem_u32(smc);
    const int tid = threadIdx.x, wid = tid >> 5, lane = tid & 31;
    const int node0 = blockIdx.x * 128;
    float* sB = (float*)(smc + OFF_BIAS);
    float* sBo = (float*)(smc + OFF_BIAS + 512);
    if (tid < 128) sB[tid] = bsv[tid] + bnv[tid];
    if (FUSE && tid < 64) sBo[tid] = bout[tid];

    // issue chunk c (A hi/lo + B) as one cp.async group
    auto issueChunk = [&](int c) {
        const __half* hi = (c >= 2) ? Nhi : Shi;
        const __half* lo = (c >= 2) ? Nlo : Slo;
        const size_t kof = (size_t)(c & 1) * 64;
        const uint32_t ab = sb + (c & 1) * 32768;
        #pragma unroll
        for (int g = tid; g < 1024; g += 512) {
            int r = g >> 3, kk = (g & 7) * 8;
            uint32_t doff = SWZ((uint32_t)(r * 128 + kk * 2));
            size_t soff = (size_t)(node0 + r) * F + kof + kk;
            cp16(ab + doff, hi + soff);
            cp16(ab + 16384 + doff, lo + soff);
        }
        const uint32_t bb = sb + OFF_B + (c & 1) * 16384;
        #pragma unroll
        for (int g = tid; g < 1024; g += 512) {
            int n = g >> 3, kk = (g & 7) * 8;
            cp16(bb + SWZ((uint32_t)(n * 128 + kk * 2)),
                 Wh + n * 256 + c * 64 + kk);
        }
        CP_COMMIT;
    };

    // lane-invariant ldmatrix bases (4 warps N x 4 warps M, MI=2)
    const int wn = (wid & 3) * 32;
    const int wm = (wid >> 2) * 32;
    const int ar = wm + (lane & 15);
    const uint32_t a_base = (uint32_t)(ar * 128 + (lane >> 4) * 16);
    const uint32_t a_mask = (uint32_t)((ar & 7) << 4);
    const int br = wn + (lane & 7) + ((lane >> 4) << 3);
    const uint32_t b_base = (uint32_t)(br * 128 + ((lane >> 3) & 1) * 16);
    const uint32_t b_mask = (uint32_t)((br & 7) << 4);

    float acc[2][4][4];
    #pragma unroll
    for (int mi = 0; mi < 2; mi++)
        #pragma unroll
        for (int ni = 0; ni < 4; ni++)
            #pragma unroll
            for (int q = 0; q < 4; q++) acc[mi][ni][q] = 0.f;

    // prologue: WO cps fold into chunk0's group; then chunk0 + chunk1
    if (FUSE) {
        #pragma unroll
        for (int g = tid; g < 1024; g += 512) {
            int n = g >> 4, kk = (g & 15) * 8;
            int chunk = kk >> 6, lc = kk & 63;
            uint32_t doff = (uint32_t)(OFF_WO + chunk * 8192) +
                            SWZ((uint32_t)(n * 128 + lc * 2));
            cp16(sb + doff, WOh + n * 128 + kk);
        }
    }
    issueChunk(0);
    issueChunk(1);

    #pragma unroll 1
    for (int c = 0; c < 4; c++) {
        if (c < 3) CP_WAIT(1); else CP_WAIT(0);
        __syncthreads();
        const uint32_t ahi = sb + (c & 1) * 32768;
        const uint32_t alo = ahi + 16384;
        const uint32_t bhib = sb + OFF_B + (c & 1) * 16384;
        #pragma unroll
        for (int ks = 0; ks < 4; ks++) {
            uint32_t ah[2][4], al[2][4], bh[4][2];
            const uint32_t ka = (a_base + ks * 32) ^ a_mask;
            #pragma unroll
            for (int mi = 0; mi < 2; mi++) {
                ldsm4(ah[mi], ahi + ka + mi * 2048);
                ldsm4(al[mi], alo + ka + mi * 2048);
            }
            const uint32_t kb = (b_base + ks * 32) ^ b_mask;
            ldsm4(&bh[0][0], bhib + kb);
            ldsm4(&bh[2][0], bhib + kb + 2048);
            #pragma unroll
            for (int mi = 0; mi < 2; mi++)
                #pragma unroll
                for (int ni = 0; ni < 4; ni++)
                    mma16816(acc[mi][ni], ah[mi], bh[ni]);
            #pragma unroll
            for (int mi = 0; mi < 2; mi++)
                #pragma unroll
                for (int ni = 0; ni < 4; ni++)
                    mma16816(acc[mi][ni], al[mi], bh[ni]);
        }
        if (c < 2) {
            __syncthreads();
            issueChunk(c + 2);
        }
    }

    const int erow = wm + (lane >> 2);
    const int ecol = wn + (lane & 3) * 2;

    if (!FUSE) {
        // epilogue: bias (+relu) then split to hi/lo fp16 planes
        #pragma unroll
        for (int mi = 0; mi < 2; mi++) {
            #pragma unroll
            for (int h = 0; h < 2; h++) {
                const int gr = node0 + erow + mi * 16 + h * 8;
                if (gr >= N_NODES) continue;
                #pragma unroll
                for (int ni = 0; ni < 4; ni++) {
                    const int cc = ecol + ni * 8;
                    float ox = acc[mi][ni][2 * h] + sB[cc];
                    float oy = acc[mi][ni][2 * h + 1] + sB[cc + 1];
                    if (RELU) { ox = fmaxf(ox, 0.f); oy = fmaxf(oy, 0.f); }
                    uint32_t hi2 = pk_h(ox, oy);
                    float2 f = up_h(hi2);
                    uint32_t lo2 = pk_h(ox - f.x, oy - f.y);
                    size_t idx = (size_t)gr * F + cc;
                    *(uint32_t*)((char*)Yhi + idx * 2) = hi2;
                    *(uint32_t*)((char*)Ylo + idx * 2) = lo2;
                }
            }
        }
        return;
    }

    // ---- FUSE: pack h2 tile (bias, no relu) into smem split fp16 ----------
    __syncthreads();
    #pragma unroll
    for (int mi = 0; mi < 2; mi++) {
        #pragma unroll
        for (int h = 0; h < 2; h++) {
            const int r = erow + mi * 16 + h * 8;
            #pragma unroll
            for (int ni = 0; ni < 4; ni++) {
                const int cc = ecol + ni * 8;
                float ox = acc[mi][ni][2 * h] + sB[cc];
                float oy = acc[mi][ni][2 * h + 1] + sB[cc + 1];
                uint32_t hi2 = pk_h(ox, oy);
                float2 f = up_h(hi2);
                uint32_t lo2 = pk_h(ox - f.x, oy - f.y);
                const int chunk = cc >> 6, lc = cc & 63;
                uint32_t off = SWZ((uint32_t)(r * 128 + lc * 2));
                *(uint32_t*)(smc + chunk * 16384 + off) = hi2;
                *(uint32_t*)(smc + 32768 + chunk * 16384 + off) = lo2;
            }
        }
    }
    __syncthreads();

    // ---- FUSE: h2 @ W_out + bout -> Yout (128 x 64, K=128) ----------------
    const int wn2 = (wid & 1) * 32;
    const int wm2 = (wid >> 1) * 16;
    const int ar2 = wm2 + (lane & 15);
    const uint32_t a_base2 = (uint32_t)(ar2 * 128 + (lane >> 4) * 16);
    const uint32_t a_mask2 = (uint32_t)((ar2 & 7) << 4);
    const int br2 = wn2 + (lane & 7) + ((lane >> 4) << 3);
    const uint32_t b_base2 = (uint32_t)(br2 * 128 + ((lane >> 3) & 1) * 16);
    const uint32_t b_mask2 = (uint32_t)((br2 & 7) << 4);

    float acc2[4][4];
    #pragma unroll
    for (int ni = 0; ni < 4; ni++)
        #pragma unroll
        for (int q = 0; q < 4; q++) acc2[ni][q] = 0.f;

    #pragma unroll
    for (int c = 0; c < 2; c++) {
        const uint32_t ahi = sb + c * 16384;
        const uint32_t alo = sb + 32768 + c * 16384;
        const uint32_t bhib = sb + OFF_WO + c * 8192;
        #pragma unroll
        for (int ks = 0; ks < 4; ks++) {
            uint32_t ah[4], al[4], bh[4][2];
            const uint32_t ka = (a_base2 + ks * 32) ^ a_mask2;
            ldsm4(ah, ahi + ka);
            ldsm4(al, alo + ka);
            const uint32_t kb = (b_base2 + ks * 32) ^ b_mask2;
            ldsm4(&bh[0][0], bhib + kb);
            ldsm4(&bh[2][0], bhib + kb + 2048);
            #pragma unroll
            for (int ni = 0; ni < 4; ni++) mma16816(acc2[ni], ah, bh[ni]);
            #pragma unroll
            for (int ni = 0; ni < 4; ni++) mma16816(acc2[ni], al, bh[ni]);
        }
    }

    const int erow2 = wm2 + (lane >> 2);
    const int ecol2 = wn2 + (lane & 3) * 2;
    #pragma unroll
    for (int h = 0; h < 2; h++) {
        const int gr = node0 + erow2 + h * 8;
        if (gr >= N_NODES) continue;
        float* yp = Yout + (size_t)gr * 64;
        #pragma unroll
        for (int ni = 0; ni < 4; ni++) {
            float2 o;
            o.x = acc2[ni][2 * h] + sBo[ecol2 + ni * 8];
            o.y = acc2[ni][2 * h + 1] + sBo[ecol2 + ni * 8 + 1];
            *(float2*)(yp + ecol2 + ni * 8) = o;
        }
    }
}

// ---------------------------------------------------------------------------
extern "C" void kernel_launch(void* const* d_in, const int* in_sizes, int n_in,
                              void* d_out, int out_size) {
    const float* feats = (const float*)d_in[0];
    const int* src = (const int*)d_in[1];
    const int* dst = (const int*)d_in[2];
    const float* Ws[3] = {(const float*)d_in[3], (const float*)d_in[7],
                          (const float*)d_in[11]};
    const float* bs[3] = {(const float*)d_in[4], (const float*)d_in[8],
                          (const float*)d_in[12]};
    const float* Wn[3] = {(const float*)d_in[5], (const float*)d_in[9],
                          (const float*)d_in[13]};
    const float* bn[3] = {(const float*)d_in[6], (const float*)d_in[10],
                          (const float*)d_in[14]};
    const float* Wout = (const float*)d_in[15];
    const float* bout = (const float*)d_in[16];

    __half *fhi, *flo, *h0hi, *h0lo, *h1hi, *h1lo, *ahi, *alo, *wh;
    cudaGetSymbolAddress((void**)&fhi, g_fhi);
    cudaGetSymbolAddress((void**)&flo, g_flo);
    cudaGetSymbolAddress((void**)&h0hi, g_h0hi);
    cudaGetSymbolAddress((void**)&h0lo, g_h0lo);
    cudaGetSymbolAddress((void**)&h1hi, g_h1hi);
    cudaGetSymbolAddress((void**)&h1lo, g_h1lo);
    cudaGetSymbolAddress((void**)&ahi, g_ahi);
    cudaGetSymbolAddress((void**)&alo, g_alo);
    cudaGetSymbolAddress((void**)&wh, g_wh);

    const int SMEM_DUAL = 98304 + 1024;   //  99,328
    const int SMEM_FUSE = 114688 + 1024;  // 115,712

    auto kRelu = sage_mma<true, false>;
    auto kFuse = sage_mma<false, true>;
    cudaFuncSetAttribute((const void*)kRelu,
                         cudaFuncAttributeMaxDynamicSharedMemorySize, SMEM_DUAL);
    cudaFuncSetAttribute((const void*)kFuse,
                         cudaFuncAttributeMaxDynamicSharedMemorySize, SMEM_FUSE);

    const int NPART = (N_NODES + 1023) / 1024;  // 98
    init_kernel<<<(W_TOTAL + 255) / 256, 256>>>(Ws[0], Wn[0], Ws[1], Wn[1],
                                                Ws[2], Wn[2], Wout);
    featconv_kernel<<<(N_NODES * 32 + 255) / 256, 256>>>(feats);
    count_kernel<<<(N_EDGES + 255) / 256, 256>>>(dst);
    scanall_kernel<<<NPART, 1024>>>();
    fill_kernel<<<(N_EDGES + 255) / 256, 256>>>(src, dst);

    const int AGG_BLOCKS = (N_NODES * 32 + 255) / 256;
    const int GB = (N_NODES + 127) / 128;  // 782

    agg_kernel<<<AGG_BLOCKS, 256>>>(fhi, flo);
    kRelu<<<GB, 512, SMEM_DUAL>>>(fhi, flo, ahi, alo, wh, bs[0], bn[0], h0hi,
                                  h0lo, nullptr, nullptr, nullptr);
    agg_kernel<<<AGG_BLOCKS, 256>>>(h0hi, h0lo);
    kRelu<<<GB, 512, SMEM_DUAL>>>(h0hi, h0lo, ahi, alo, wh + 32768, bs[1],
                                  bn[1], h1hi, h1lo, nullptr, nullptr,
                                  nullptr);
    agg_kernel<<<AGG_BLOCKS, 256>>>(h1hi, h1lo);
    kFuse<<<GB, 512, SMEM_FUSE>>>(h1hi, h1lo, ahi, alo, wh + 65536, bs[2],
                                  bn[2], nullptr, nullptr, wh + 98304, bout,
                                  (float*)d_out);
}